// round 1
// baseline (speedup 1.0000x reference)
#include <cuda_runtime.h>
#include <cuda_bf16.h>
#include <math.h>

#define BATCH 2
#define L 1024
#define BL 2048          // BATCH * L
#define DIM 1152
#define NHEADS 16
#define HDIM 72
#define FF 4304
#define NLAYERS 4
#define PATCHD 768       // 16*16*3
#define EPS 1e-6f

// ---------------- static scratch (zero-init .bss, no allocation) ----------------
__device__ float g_patches[BL * PATCHD];
__device__ float g_x[BL * DIM];
__device__ float g_h[BL * DIM];
__device__ float g_q[BL * DIM];
__device__ float g_k[BL * DIM];
__device__ float g_v[BL * DIM];
__device__ float g_att[BL * DIM];
__device__ float g_o[BL * DIM];
__device__ float g_logits[(size_t)BATCH * NHEADS * L * L];
__device__ float g_gate[BL * FF];
__device__ float g_up[BL * FF];

// ---------------- patchify: (2*img-1) gather into [BL, 768] ----------------
__global__ void patchify_kernel(const float* __restrict__ img, float* __restrict__ P) {
    int idx = blockIdx.x * blockDim.x + threadIdx.x;
    if (idx >= BL * PATCHD) return;
    int bl = idx / PATCHD, j = idx % PATCHD;
    int b = bl >> 10, l = bl & 1023;
    int gy = l >> 5, gx = l & 31;
    int py = j / 48, r = j % 48;
    int px = r / 3, c = r % 3;
    int row = gy * 16 + py, col = gx * 16 + px;
    P[idx] = 2.0f * img[(((size_t)b * 512 + row) * 512 + col) * 3 + c] - 1.0f;
}

// ---------------- factorized pos-emb add ----------------
__global__ void add_posemb_kernel(float* __restrict__ x, const float* __restrict__ pe) {
    int idx = blockIdx.x * blockDim.x + threadIdx.x;
    if (idx >= BL * DIM) return;
    int bl = idx / DIM, d = idx % DIM;
    int l = bl & 1023;
    int posx = l & 31, posy = l >> 5;
    x[idx] += pe[(size_t)(posx * 2 + 0) * DIM + d] + pe[(size_t)(posy * 2 + 1) * DIM + d];
}

// ---------------- generic SGEMM: C[M,N] = A[M,K] @ B[K,N] ----------------
// assumes M % 128 == 0, K % 8 == 0, N % 4 == 0; N bounds handled.
__global__ __launch_bounds__(256) void sgemm_kernel(const float* __restrict__ A,
                                                    const float* __restrict__ B,
                                                    float* __restrict__ C,
                                                    int M, int N, int K) {
    __shared__ float As[8][128];
    __shared__ float Bs[8][128];
    const int tid = threadIdx.x;
    const int tx = tid & 15, ty = tid >> 4;
    const int rowBase = blockIdx.y * 128;
    const int colBase = blockIdx.x * 128;
    const int aRow = tid >> 1;
    const int aCol = (tid & 1) * 4;
    const int bRow = tid >> 5;
    const int bCol = (tid & 31) * 4;
    const int bc = colBase + bCol;
    float acc[8][8] = {};
    const float* Aptr = A + (size_t)(rowBase + aRow) * K + aCol;
    const float* Bptr = B + (size_t)bRow * N + bc;
    for (int k0 = 0; k0 < K; k0 += 8) {
        float4 av = *(const float4*)(Aptr + k0);
        As[aCol + 0][aRow] = av.x;
        As[aCol + 1][aRow] = av.y;
        As[aCol + 2][aRow] = av.z;
        As[aCol + 3][aRow] = av.w;
        float4 bv = make_float4(0.f, 0.f, 0.f, 0.f);
        if (bc < N) bv = *(const float4*)(Bptr + (size_t)k0 * N);
        *(float4*)&Bs[bRow][bCol] = bv;
        __syncthreads();
#pragma unroll
        for (int kk = 0; kk < 8; ++kk) {
            float ra[8], rb[8];
            *(float4*)(ra)     = *(const float4*)&As[kk][ty * 8];
            *(float4*)(ra + 4) = *(const float4*)&As[kk][ty * 8 + 4];
            *(float4*)(rb)     = *(const float4*)&Bs[kk][tx * 8];
            *(float4*)(rb + 4) = *(const float4*)&Bs[kk][tx * 8 + 4];
#pragma unroll
            for (int i = 0; i < 8; i++)
#pragma unroll
                for (int j = 0; j < 8; j++) acc[i][j] += ra[i] * rb[j];
        }
        __syncthreads();
    }
#pragma unroll
    for (int i = 0; i < 8; i++) {
        int r = rowBase + ty * 8 + i;
#pragma unroll
        for (int jj = 0; jj < 8; jj += 4) {
            int c = colBase + tx * 8 + jj;
            if (c < N)
                *(float4*)(C + (size_t)r * N + c) =
                    make_float4(acc[i][jj], acc[i][jj + 1], acc[i][jj + 2], acc[i][jj + 3]);
        }
    }
}

// ---------------- row RMSNorm: out = x * rsqrt(mean(x^2)+eps) * (1+scale) ----------------
__global__ void rmsnorm_kernel(const float* __restrict__ in, const float* __restrict__ scale,
                               float* __restrict__ out) {
    int row = blockIdx.x;
    const float* p = in + (size_t)row * DIM;
    float s = 0.f;
    for (int i = threadIdx.x; i < DIM; i += 256) { float v = p[i]; s += v * v; }
    __shared__ float red[256];
    red[threadIdx.x] = s; __syncthreads();
    for (int st = 128; st > 0; st >>= 1) {
        if (threadIdx.x < st) red[threadIdx.x] += red[threadIdx.x + st];
        __syncthreads();
    }
    float rs = rsqrtf(red[0] / (float)DIM + EPS);
    for (int i = threadIdx.x; i < DIM; i += 256)
        out[(size_t)row * DIM + i] = p[i] * rs * (1.f + scale[i]);
}

// ---------------- residual add of RMSNormed branch: x += rms(o)*(1+scale) ----------------
__global__ void resid_rms_add_kernel(float* __restrict__ x, const float* __restrict__ o,
                                     const float* __restrict__ scale) {
    int row = blockIdx.x;
    const float* p = o + (size_t)row * DIM;
    float s = 0.f;
    for (int i = threadIdx.x; i < DIM; i += 256) { float v = p[i]; s += v * v; }
    __shared__ float red[256];
    red[threadIdx.x] = s; __syncthreads();
    for (int st = 128; st > 0; st >>= 1) {
        if (threadIdx.x < st) red[threadIdx.x] += red[threadIdx.x + st];
        __syncthreads();
    }
    float rs = rsqrtf(red[0] / (float)DIM + EPS);
    for (int i = threadIdx.x; i < DIM; i += 256)
        x[(size_t)row * DIM + i] += p[i] * rs * (1.f + scale[i]);
}

// ---------------- per-head RMS (+ optional 2D RoPE), warp per (token, head) ----------------
__global__ void head_rms_rope_kernel(float* __restrict__ t, const float* __restrict__ scale,
                                     int do_rope) {
    int warp = threadIdx.x >> 5, lane = threadIdx.x & 31;
    int item = blockIdx.x * 8 + warp;        // (token, head) pair
    int token = item >> 4;
    int head = item & 15;
    float* p = t + (size_t)token * DIM + head * HDIM;
    float v0 = p[lane];
    float v1 = p[lane + 32];
    float v2 = (lane < 8) ? p[lane + 64] : 0.f;
    float s = v0 * v0 + v1 * v1 + v2 * v2;
#pragma unroll
    for (int off = 16; off; off >>= 1) s += __shfl_xor_sync(0xffffffffu, s, off);
    float rs = rsqrtf(s / (float)HDIM + EPS);
    float n0 = v0 * rs * (1.f + scale[lane]);
    float n1 = v1 * rs * (1.f + scale[lane + 32]);
    float n2 = (lane < 8) ? v2 * rs * (1.f + scale[lane + 64]) : 0.f;
    if (!do_rope) {
        p[lane] = n0; p[lane + 32] = n1;
        if (lane < 8) p[lane + 64] = n2;
        return;
    }
    __shared__ float buf[8][HDIM];
    buf[warp][lane] = n0;
    buf[warp][lane + 32] = n1;
    if (lane < 8) buf[warp][lane + 64] = n2;
    __syncwarp();
    int l = token & 1023;
    float posx = (float)(l & 31), posy = (float)(l >> 5);
    // 36 rotation pairs: pp<18 -> x-axis chunk (d1=pp, d2=pp+18);
    // pp>=18 -> y-axis chunk (d1=pp+18, d2=pp+36)
    for (int pp = lane; pp < 36; pp += 32) {
        int j = (pp < 18) ? pp : (pp - 18);
        float pos = (pp < 18) ? posx : posy;
        int d1 = (pp < 18) ? pp : (pp + 18);
        int d2 = d1 + 18;
        float ts = powf(100.f, (float)j / 18.f);
        float ang = pos / ts;
        float sn, cs;
        sincosf(ang, &sn, &cs);
        float a = buf[warp][d1], b2 = buf[warp][d2];
        p[d1] = a * cs - b2 * sn;
        p[d2] = b2 * cs + a * sn;
    }
}

// ---------------- batched Q K^T (per b,n): logits[bn,t,s] = scale * sum_h q k ----------------
__global__ __launch_bounds__(256) void qk_kernel(const float* __restrict__ q,
                                                 const float* __restrict__ k,
                                                 float* __restrict__ logits) {
    int bn = blockIdx.z;
    int b = bn >> 4, n = bn & 15;
    const float* qb = q + (size_t)b * L * DIM + n * HDIM;
    const float* kb = k + (size_t)b * L * DIM + n * HDIM;
    __shared__ float Qs[64][HDIM + 1];
    __shared__ float Ks[64][HDIM + 1];
    int t0 = blockIdx.y * 64, s0 = blockIdx.x * 64;
    for (int idx = threadIdx.x; idx < 64 * HDIM; idx += 256) {
        int r = idx / HDIM, d = idx % HDIM;
        Qs[r][d] = qb[(size_t)(t0 + r) * DIM + d];
        Ks[r][d] = kb[(size_t)(s0 + r) * DIM + d];
    }
    __syncthreads();
    int tx = threadIdx.x & 15, ty = threadIdx.x >> 4;
    float acc[4][4] = {};
#pragma unroll 4
    for (int d = 0; d < HDIM; ++d) {
        float qv[4], kv[4];
#pragma unroll
        for (int i = 0; i < 4; i++) qv[i] = Qs[ty * 4 + i][d];
#pragma unroll
        for (int j = 0; j < 4; j++) kv[j] = Ks[tx * 4 + j][d];
#pragma unroll
        for (int i = 0; i < 4; i++)
#pragma unroll
            for (int j = 0; j < 4; j++) acc[i][j] += qv[i] * kv[j];
    }
    const float sc = rsqrtf((float)HDIM);
    float* out = logits + (size_t)bn * L * L;
#pragma unroll
    for (int i = 0; i < 4; i++)
#pragma unroll
        for (int j = 0; j < 4; j++)
            out[(size_t)(t0 + ty * 4 + i) * L + (s0 + tx * 4 + j)] = acc[i][j] * sc;
}

// ---------------- softmax over rows of 1024 ----------------
__global__ void softmax_kernel(float* __restrict__ lg) {
    float* row = lg + (size_t)blockIdx.x * L;
    int t = threadIdx.x;
    float vals[4];
    float m = -1e30f;
#pragma unroll
    for (int i = 0; i < 4; i++) { vals[i] = row[t + i * 256]; m = fmaxf(m, vals[i]); }
    __shared__ float red[256];
    red[t] = m; __syncthreads();
    for (int st = 128; st > 0; st >>= 1) {
        if (t < st) red[t] = fmaxf(red[t], red[t + st]);
        __syncthreads();
    }
    m = red[0]; __syncthreads();
    float s = 0.f;
#pragma unroll
    for (int i = 0; i < 4; i++) { vals[i] = __expf(vals[i] - m); s += vals[i]; }
    red[t] = s; __syncthreads();
    for (int st = 128; st > 0; st >>= 1) {
        if (t < st) red[t] += red[t + st];
        __syncthreads();
    }
    float inv = 1.f / red[0];
#pragma unroll
    for (int i = 0; i < 4; i++) row[t + i * 256] = vals[i] * inv;
}

// ---------------- attn = probs @ V (per b,n) : out[b,t,n,h] ----------------
__global__ void av_kernel(const float* __restrict__ probs, const float* __restrict__ v,
                          float* __restrict__ out) {
    int bn = blockIdx.y;
    int b = bn >> 4, n = bn & 15;
    int r0 = blockIdx.x * 4;
    int tx = threadIdx.x;   // 0..71 (head dim)
    int ty = threadIdx.y;   // 0..3  (row)
    int tid = ty * 72 + tx; // 0..287
    __shared__ float Ps[4][64];
    __shared__ float Vs[64][HDIM + 1];
    const float* pb = probs + (size_t)bn * L * L;
    const float* vb = v + (size_t)b * L * DIM + n * HDIM;
    float acc = 0.f;
    for (int s0 = 0; s0 < L; s0 += 64) {
        if (tid < 256)
            Ps[tid >> 6][tid & 63] = pb[(size_t)(r0 + (tid >> 6)) * L + s0 + (tid & 63)];
        for (int idx = tid; idx < 64 * HDIM; idx += 288) {
            int s = idx / HDIM, d = idx % HDIM;
            Vs[s][d] = vb[(size_t)(s0 + s) * DIM + d];
        }
        __syncthreads();
#pragma unroll 8
        for (int ss = 0; ss < 64; ++ss) acc += Ps[ty][ss] * Vs[ss][tx];
        __syncthreads();
    }
    out[(size_t)(b * L + r0 + ty) * DIM + n * HDIM + tx] = acc;
}

// ---------------- GeGLU: gate = gelu_tanh(gate) * up ----------------
__global__ void geglu_kernel(float* __restrict__ gate, const float* __restrict__ up) {
    int idx = blockIdx.x * blockDim.x + threadIdx.x;
    if (idx >= BL * FF) return;
    float g = gate[idx];
    float t = 0.7978845608028654f * (g + 0.044715f * g * g * g);
    gate[idx] = 0.5f * g * (1.f + tanhf(t)) * up[idx];
}

// ---------------- final: out = (x*sqrt(D) - bias) * scale ----------------
__global__ void final_kernel(const float* __restrict__ x, const float* __restrict__ bias,
                             const float* __restrict__ scl, float* __restrict__ out) {
    int idx = blockIdx.x * blockDim.x + threadIdx.x;
    if (idx >= BL * DIM) return;
    int d = idx % DIM;
    out[idx] = (x[idx] * 33.941125496954285f - bias[d]) * scl[d];
}

// ---------------- launcher ----------------
extern "C" void kernel_launch(void* const* d_in, const int* in_sizes, int n_in,
                              void* d_out, int out_size) {
    const float* inputs    = (const float*)d_in[0];
    const float* Wp        = (const float*)d_in[1];
    const float* posemb    = (const float*)d_in[2];
    const float* Wq        = (const float*)d_in[3];
    const float* Wk        = (const float*)d_in[4];
    const float* Wv        = (const float*)d_in[5];
    const float* Wo        = (const float*)d_in[6];
    const float* Wg        = (const float*)d_in[7];
    const float* Wu        = (const float*)d_in[8];
    const float* Wd        = (const float*)d_in[9];
    const float* qn        = (const float*)d_in[10];
    const float* kn        = (const float*)d_in[11];
    const float* vn        = (const float*)d_in[12];
    const float* pre_attn  = (const float*)d_in[13];
    const float* post_attn = (const float*)d_in[14];
    const float* pre_ffw   = (const float*)d_in[15];
    const float* post_ffw  = (const float*)d_in[16];
    const float* std_bias  = (const float*)d_in[17];
    const float* std_scale = (const float*)d_in[18];
    float* out = (float*)d_out;

    float *patches, *x, *h, *q, *k, *v, *att, *o, *logits, *gate, *up;
    cudaGetSymbolAddress((void**)&patches, g_patches);
    cudaGetSymbolAddress((void**)&x, g_x);
    cudaGetSymbolAddress((void**)&h, g_h);
    cudaGetSymbolAddress((void**)&q, g_q);
    cudaGetSymbolAddress((void**)&k, g_k);
    cudaGetSymbolAddress((void**)&v, g_v);
    cudaGetSymbolAddress((void**)&att, g_att);
    cudaGetSymbolAddress((void**)&o, g_o);
    cudaGetSymbolAddress((void**)&logits, g_logits);
    cudaGetSymbolAddress((void**)&gate, g_gate);
    cudaGetSymbolAddress((void**)&up, g_up);

    // entry
    patchify_kernel<<<(BL * PATCHD + 255) / 256, 256>>>(inputs, patches);
    sgemm_kernel<<<dim3(DIM / 128, BL / 128), 256>>>(patches, Wp, x, BL, DIM, PATCHD);
    add_posemb_kernel<<<(BL * DIM + 255) / 256, 256>>>(x, posemb);

    for (int i = 0; i < NLAYERS; i++) {
        const float* Wq_i = Wq + (size_t)i * DIM * DIM;
        const float* Wk_i = Wk + (size_t)i * DIM * DIM;
        const float* Wv_i = Wv + (size_t)i * DIM * DIM;
        const float* Wo_i = Wo + (size_t)i * DIM * DIM;
        const float* Wg_i = Wg + (size_t)i * DIM * FF;
        const float* Wu_i = Wu + (size_t)i * DIM * FF;
        const float* Wd_i = Wd + (size_t)i * FF * DIM;

        // attention
        rmsnorm_kernel<<<BL, 256>>>(x, pre_attn + i * DIM, h);
        sgemm_kernel<<<dim3(DIM / 128, BL / 128), 256>>>(h, Wq_i, q, BL, DIM, DIM);
        sgemm_kernel<<<dim3(DIM / 128, BL / 128), 256>>>(h, Wk_i, k, BL, DIM, DIM);
        sgemm_kernel<<<dim3(DIM / 128, BL / 128), 256>>>(h, Wv_i, v, BL, DIM, DIM);
        head_rms_rope_kernel<<<BL * NHEADS / 8, 256>>>(q, qn + i * HDIM, 1);
        head_rms_rope_kernel<<<BL * NHEADS / 8, 256>>>(k, kn + i * HDIM, 1);
        head_rms_rope_kernel<<<BL * NHEADS / 8, 256>>>(v, vn + i * HDIM, 0);
        qk_kernel<<<dim3(L / 64, L / 64, BATCH * NHEADS), 256>>>(q, k, logits);
        softmax_kernel<<<BATCH * NHEADS * L, 256>>>(logits);
        av_kernel<<<dim3(L / 4, BATCH * NHEADS), dim3(72, 4)>>>(logits, v, att);
        sgemm_kernel<<<dim3(DIM / 128, BL / 128), 256>>>(att, Wo_i, o, BL, DIM, DIM);
        resid_rms_add_kernel<<<BL, 256>>>(x, o, post_attn + i * DIM);

        // GeGLU MLP
        rmsnorm_kernel<<<BL, 256>>>(x, pre_ffw + i * DIM, h);
        sgemm_kernel<<<dim3((FF + 127) / 128, BL / 128), 256>>>(h, Wg_i, gate, BL, FF, DIM);
        sgemm_kernel<<<dim3((FF + 127) / 128, BL / 128), 256>>>(h, Wu_i, up, BL, FF, DIM);
        geglu_kernel<<<(BL * FF + 255) / 256, 256>>>(gate, up);
        sgemm_kernel<<<dim3(DIM / 128, BL / 128), 256>>>(gate, Wd_i, o, BL, DIM, FF);
        resid_rms_add_kernel<<<BL, 256>>>(x, o, post_ffw + i * DIM);
    }

    // exit
    final_kernel<<<(BL * DIM + 255) / 256, 256>>>(x, std_bias, std_scale, out);
}

// round 3
// speedup vs baseline: 1.8892x; 1.8892x over previous
#include <cuda_runtime.h>
#include <cuda_bf16.h>
#include <math.h>

#define BATCH 2
#define L 1024
#define BL 2048          // BATCH * L
#define DIM 1152
#define NHEADS 16
#define HDIM 72
#define FF 4304
#define NLAYERS 4
#define PATCHD 768       // 16*16*3
#define EPS 1e-6f

// ---------------- static scratch (zero-init .bss, no allocation) ----------------
__device__ float g_patches[BL * PATCHD];
__device__ float g_x[BL * DIM];
__device__ float g_h[BL * DIM];
__device__ float g_q[BL * DIM];
__device__ float g_k[BL * DIM];
__device__ float g_v[BL * DIM];
__device__ float g_att[BL * DIM];
__device__ float g_o[BL * DIM];
__device__ float g_logits[(size_t)BATCH * NHEADS * L * L];
__device__ float g_gate[BL * FF];
__device__ float g_up[BL * FF];

// split f32 into hi+lo tf32 pair (3xTF32 trick: a*b ~= ah*bh + ah*bl + al*bh)
__device__ __forceinline__ void f2tf_split(float f, unsigned& hi, unsigned& lo) {
    asm("cvt.rna.tf32.f32 %0, %1;" : "=r"(hi) : "f"(f));
    float r = f - __uint_as_float(hi);
    asm("cvt.rna.tf32.f32 %0, %1;" : "=r"(lo) : "f"(r));
}

__device__ __forceinline__ void mma_tf32(float c[4], const unsigned a[4], unsigned b0,
                                         unsigned b1) {
    asm volatile(
        "mma.sync.aligned.m16n8k8.row.col.f32.tf32.tf32.f32 "
        "{%0,%1,%2,%3}, {%4,%5,%6,%7}, {%8,%9}, {%0,%1,%2,%3};"
        : "+f"(c[0]), "+f"(c[1]), "+f"(c[2]), "+f"(c[3])
        : "r"(a[0]), "r"(a[1]), "r"(a[2]), "r"(a[3]), "r"(b0), "r"(b1));
}

// 3-term precise product-accumulate
__device__ __forceinline__ void mma3(float c[4], const unsigned ah[4], const unsigned al[4],
                                     unsigned bh0, unsigned bh1, unsigned bl0, unsigned bl1) {
    mma_tf32(c, ah, bh0, bh1);
    mma_tf32(c, ah, bl0, bl1);
    mma_tf32(c, al, bh0, bh1);
}

// =====================================================================================
// NN tensor-core GEMM (3xTF32): C[M,N] = alpha * A[M,K] @ B[K,N]
// A row-major (lda), B row-major (ldb), C row-major (ldc).
// Requirements: M % 128 == 0, K % 8 == 0, N % 8 == 0 (bounds on N handled).
// av_mode: blockIdx.z = b*16+n, applies attention PV offsets.
// =====================================================================================
__global__ __launch_bounds__(256) void mma_nn(const float* __restrict__ A, int lda,
                                              const float* __restrict__ B, int ldb,
                                              float* __restrict__ C, int ldc,
                                              int M, int N, int K, int av_mode, float alpha) {
    __shared__ float As[2][128][20];   // padded: bank-conflict-free frag loads
    __shared__ float Bs[2][16][136];
    const int tid = threadIdx.x;
    if (av_mode) {
        int bn = blockIdx.z, b = bn >> 4, n = bn & 15;
        A += (size_t)bn * L * L;
        B += (size_t)b * L * DIM + n * HDIM;
        C += (size_t)b * L * DIM + n * HDIM;
    }
    const int m0 = blockIdx.y * 128, n0 = blockIdx.x * 128;
    const int aRow = tid >> 1, aK = (tid & 1) * 8;
    const int bK = tid >> 4, bN = (tid & 15) * 8;
    const bool bNvalid = (n0 + bN) < N;
    const float* Ap = A + (size_t)(m0 + aRow) * lda + aK;
    const float* Bp = B + (size_t)bK * ldb + n0 + bN;

    const int lane = tid & 31, warp = tid >> 5;
    const int g = lane >> 2, t = lane & 3;
    const int wM = (warp >> 2) * 64, wN = (warp & 3) * 32;

    float acc[4][4][4];
#pragma unroll
    for (int i = 0; i < 4; i++)
#pragma unroll
        for (int j = 0; j < 4; j++)
#pragma unroll
            for (int r = 0; r < 4; r++) acc[i][j][r] = 0.f;

    const int nT = (K + 15) >> 4;
    float4 ra0, ra1, rb0, rb1;

    auto LOAD = [&](int k0) {
        bool av = (k0 + aK) < K;
        ra0 = av ? *(const float4*)(Ap + k0) : make_float4(0, 0, 0, 0);
        ra1 = av ? *(const float4*)(Ap + k0 + 4) : make_float4(0, 0, 0, 0);
        bool bv = bNvalid && (k0 + bK) < K;
        rb0 = bv ? *(const float4*)(Bp + (size_t)k0 * ldb) : make_float4(0, 0, 0, 0);
        rb1 = bv ? *(const float4*)(Bp + (size_t)k0 * ldb + 4) : make_float4(0, 0, 0, 0);
    };
    auto STORE = [&](int buf) {
        *(float4*)&As[buf][aRow][aK] = ra0;
        *(float4*)&As[buf][aRow][aK + 4] = ra1;
        *(float4*)&Bs[buf][bK][bN] = rb0;
        *(float4*)&Bs[buf][bK][bN + 4] = rb1;
    };

    LOAD(0); STORE(0); __syncthreads();
    for (int tile = 0; tile < nT; ++tile) {
        int buf = tile & 1;
        if (tile + 1 < nT) LOAD((tile + 1) << 4);
#pragma unroll
        for (int ks = 0; ks < 2; ++ks) {
            unsigned ah[4][4], al[4][4], bh[4][2], bl[4][2];
#pragma unroll
            for (int mt = 0; mt < 4; mt++) {
                int r = wM + mt * 16 + g;
                f2tf_split(As[buf][r][ks * 8 + t],          ah[mt][0], al[mt][0]);
                f2tf_split(As[buf][r + 8][ks * 8 + t],      ah[mt][1], al[mt][1]);
                f2tf_split(As[buf][r][ks * 8 + t + 4],      ah[mt][2], al[mt][2]);
                f2tf_split(As[buf][r + 8][ks * 8 + t + 4],  ah[mt][3], al[mt][3]);
            }
#pragma unroll
            for (int nt = 0; nt < 4; nt++) {
                int c = wN + nt * 8 + g;
                f2tf_split(Bs[buf][ks * 8 + t][c],     bh[nt][0], bl[nt][0]);
                f2tf_split(Bs[buf][ks * 8 + t + 4][c], bh[nt][1], bl[nt][1]);
            }
#pragma unroll
            for (int mt = 0; mt < 4; mt++)
#pragma unroll
                for (int nt = 0; nt < 4; nt++)
                    mma3(acc[mt][nt], ah[mt], al[mt], bh[nt][0], bh[nt][1],
                         bl[nt][0], bl[nt][1]);
        }
        if (tile + 1 < nT) STORE(buf ^ 1);
        __syncthreads();
    }
#pragma unroll
    for (int mt = 0; mt < 4; mt++) {
        int r = m0 + wM + mt * 16 + g;
#pragma unroll
        for (int nt = 0; nt < 4; nt++) {
            int c = n0 + wN + nt * 8 + 2 * t;
            if (c < N) {
                float* p0 = C + (size_t)r * ldc + c;
                float* p1 = C + (size_t)(r + 8) * ldc + c;
                *(float2*)p0 = make_float2(acc[mt][nt][0] * alpha, acc[mt][nt][1] * alpha);
                *(float2*)p1 = make_float2(acc[mt][nt][2] * alpha, acc[mt][nt][3] * alpha);
            }
        }
    }
}

// =====================================================================================
// NT tensor-core GEMM for QK^T (3xTF32): logits[bn][t][s] = alpha * sum_h Q[t][h]K[s][h]
// =====================================================================================
__global__ __launch_bounds__(256) void mma_nt_qk(const float* __restrict__ Q,
                                                 const float* __restrict__ Km,
                                                 float* __restrict__ Cl, float alpha) {
    __shared__ float As[2][128][20];
    __shared__ float Bsn[2][128][20];
    const int tid = threadIdx.x;
    const int bn = blockIdx.z, b = bn >> 4, n = bn & 15;
    const float* A = Q + (size_t)b * L * DIM + n * HDIM;
    const float* B = Km + (size_t)b * L * DIM + n * HDIM;
    float* C = Cl + (size_t)bn * L * L;
    const int lda = DIM, ldb = DIM, ldc = L, K = HDIM;

    const int m0 = blockIdx.y * 128, n0 = blockIdx.x * 128;
    const int aRow = tid >> 1, aK = (tid & 1) * 8;
    const float* Ap = A + (size_t)(m0 + aRow) * lda + aK;
    const float* Bp = B + (size_t)(n0 + aRow) * ldb + aK;

    const int lane = tid & 31, warp = tid >> 5;
    const int g = lane >> 2, t = lane & 3;
    const int wM = (warp >> 2) * 64, wN = (warp & 3) * 32;

    float acc[4][4][4];
#pragma unroll
    for (int i = 0; i < 4; i++)
#pragma unroll
        for (int j = 0; j < 4; j++)
#pragma unroll
            for (int r = 0; r < 4; r++) acc[i][j][r] = 0.f;

    const int nT = (K + 15) >> 4;   // 5 tiles for K=72
    float4 ra0, ra1, rb0, rb1;
    auto LOAD = [&](int k0) {
        bool v0 = (k0 + aK) < K;
        bool v1 = (k0 + aK + 4) < K;
        ra0 = v0 ? *(const float4*)(Ap + k0) : make_float4(0, 0, 0, 0);
        ra1 = v1 ? *(const float4*)(Ap + k0 + 4) : make_float4(0, 0, 0, 0);
        rb0 = v0 ? *(const float4*)(Bp + k0) : make_float4(0, 0, 0, 0);
        rb1 = v1 ? *(const float4*)(Bp + k0 + 4) : make_float4(0, 0, 0, 0);
    };
    auto STORE = [&](int buf) {
        *(float4*)&As[buf][aRow][aK] = ra0;
        *(float4*)&As[buf][aRow][aK + 4] = ra1;
        *(float4*)&Bsn[buf][aRow][aK] = rb0;
        *(float4*)&Bsn[buf][aRow][aK + 4] = rb1;
    };

    LOAD(0); STORE(0); __syncthreads();
    for (int tile = 0; tile < nT; ++tile) {
        int buf = tile & 1;
        if (tile + 1 < nT) LOAD((tile + 1) << 4);
#pragma unroll
        for (int ks = 0; ks < 2; ++ks) {
            unsigned ah[4][4], al[4][4], bh[4][2], bl[4][2];
#pragma unroll
            for (int mt = 0; mt < 4; mt++) {
                int r = wM + mt * 16 + g;
                f2tf_split(As[buf][r][ks * 8 + t],          ah[mt][0], al[mt][0]);
                f2tf_split(As[buf][r + 8][ks * 8 + t],      ah[mt][1], al[mt][1]);
                f2tf_split(As[buf][r][ks * 8 + t + 4],      ah[mt][2], al[mt][2]);
                f2tf_split(As[buf][r + 8][ks * 8 + t + 4],  ah[mt][3], al[mt][3]);
            }
#pragma unroll
            for (int nt = 0; nt < 4; nt++) {
                int c = wN + nt * 8 + g;
                f2tf_split(Bsn[buf][c][ks * 8 + t],     bh[nt][0], bl[nt][0]);
                f2tf_split(Bsn[buf][c][ks * 8 + t + 4], bh[nt][1], bl[nt][1]);
            }
#pragma unroll
            for (int mt = 0; mt < 4; mt++)
#pragma unroll
                for (int nt = 0; nt < 4; nt++)
                    mma3(acc[mt][nt], ah[mt], al[mt], bh[nt][0], bh[nt][1],
                         bl[nt][0], bl[nt][1]);
        }
        if (tile + 1 < nT) STORE(buf ^ 1);
        __syncthreads();
    }
#pragma unroll
    for (int mt = 0; mt < 4; mt++) {
        int r = m0 + wM + mt * 16 + g;
#pragma unroll
        for (int nt = 0; nt < 4; nt++) {
            int c = n0 + wN + nt * 8 + 2 * t;
            float* p0 = C + (size_t)r * ldc + c;
            float* p1 = C + (size_t)(r + 8) * ldc + c;
            *(float2*)p0 = make_float2(acc[mt][nt][0] * alpha, acc[mt][nt][1] * alpha);
            *(float2*)p1 = make_float2(acc[mt][nt][2] * alpha, acc[mt][nt][3] * alpha);
        }
    }
}

// ---------------- patchify: (2*img-1) gather into [BL, 768] ----------------
__global__ void patchify_kernel(const float* __restrict__ img, float* __restrict__ P) {
    int idx = blockIdx.x * blockDim.x + threadIdx.x;
    if (idx >= BL * PATCHD) return;
    int bl = idx / PATCHD, j = idx % PATCHD;
    int b = bl >> 10, l = bl & 1023;
    int gy = l >> 5, gx = l & 31;
    int py = j / 48, r = j % 48;
    int px = r / 3, c = r % 3;
    int row = gy * 16 + py, col = gx * 16 + px;
    P[idx] = 2.0f * img[(((size_t)b * 512 + row) * 512 + col) * 3 + c] - 1.0f;
}

// ---------------- factorized pos-emb add ----------------
__global__ void add_posemb_kernel(float* __restrict__ x, const float* __restrict__ pe) {
    int idx = blockIdx.x * blockDim.x + threadIdx.x;
    if (idx >= BL * DIM) return;
    int bl = idx / DIM, d = idx % DIM;
    int l = bl & 1023;
    int posx = l & 31, posy = l >> 5;
    x[idx] += pe[(size_t)(posx * 2 + 0) * DIM + d] + pe[(size_t)(posy * 2 + 1) * DIM + d];
}

// ---------------- row RMSNorm ----------------
__global__ void rmsnorm_kernel(const float* __restrict__ in, const float* __restrict__ scale,
                               float* __restrict__ out) {
    int row = blockIdx.x;
    const float* p = in + (size_t)row * DIM;
    float s = 0.f;
    for (int i = threadIdx.x; i < DIM; i += 256) { float v = p[i]; s += v * v; }
    __shared__ float red[256];
    red[threadIdx.x] = s; __syncthreads();
    for (int st = 128; st > 0; st >>= 1) {
        if (threadIdx.x < st) red[threadIdx.x] += red[threadIdx.x + st];
        __syncthreads();
    }
    float rs = rsqrtf(red[0] / (float)DIM + EPS);
    for (int i = threadIdx.x; i < DIM; i += 256)
        out[(size_t)row * DIM + i] = p[i] * rs * (1.f + scale[i]);
}

// ---------------- residual add of RMSNormed branch ----------------
__global__ void resid_rms_add_kernel(float* __restrict__ x, const float* __restrict__ o,
                                     const float* __restrict__ scale) {
    int row = blockIdx.x;
    const float* p = o + (size_t)row * DIM;
    float s = 0.f;
    for (int i = threadIdx.x; i < DIM; i += 256) { float v = p[i]; s += v * v; }
    __shared__ float red[256];
    red[threadIdx.x] = s; __syncthreads();
    for (int st = 128; st > 0; st >>= 1) {
        if (threadIdx.x < st) red[threadIdx.x] += red[threadIdx.x + st];
        __syncthreads();
    }
    float rs = rsqrtf(red[0] / (float)DIM + EPS);
    for (int i = threadIdx.x; i < DIM; i += 256)
        x[(size_t)row * DIM + i] += p[i] * rs * (1.f + scale[i]);
}

// ---------------- per-head RMS (+ optional 2D RoPE), warp per (token, head) ----------------
__global__ void head_rms_rope_kernel(float* __restrict__ t, const float* __restrict__ scale,
                                     int do_rope) {
    int warp = threadIdx.x >> 5, lane = threadIdx.x & 31;
    int item = blockIdx.x * 8 + warp;
    int token = item >> 4;
    int head = item & 15;
    float* p = t + (size_t)token * DIM + head * HDIM;
    float v0 = p[lane];
    float v1 = p[lane + 32];
    float v2 = (lane < 8) ? p[lane + 64] : 0.f;
    float s = v0 * v0 + v1 * v1 + v2 * v2;
#pragma unroll
    for (int off = 16; off; off >>= 1) s += __shfl_xor_sync(0xffffffffu, s, off);
    float rs = rsqrtf(s / (float)HDIM + EPS);
    float n0 = v0 * rs * (1.f + scale[lane]);
    float n1 = v1 * rs * (1.f + scale[lane + 32]);
    float n2 = (lane < 8) ? v2 * rs * (1.f + scale[lane + 64]) : 0.f;
    if (!do_rope) {
        p[lane] = n0; p[lane + 32] = n1;
        if (lane < 8) p[lane + 64] = n2;
        return;
    }
    __shared__ float buf[8][HDIM];
    buf[warp][lane] = n0;
    buf[warp][lane + 32] = n1;
    if (lane < 8) buf[warp][lane + 64] = n2;
    __syncwarp();
    int l = token & 1023;
    float posx = (float)(l & 31), posy = (float)(l >> 5);
    for (int pp = lane; pp < 36; pp += 32) {
        int j = (pp < 18) ? pp : (pp - 18);
        float pos = (pp < 18) ? posx : posy;
        int d1 = (pp < 18) ? pp : (pp + 18);
        int d2 = d1 + 18;
        float ts = powf(100.f, (float)j / 18.f);
        float ang = pos / ts;
        float sn, cs;
        sincosf(ang, &sn, &cs);
        float a = buf[warp][d1], b2 = buf[warp][d2];
        p[d1] = a * cs - b2 * sn;
        p[d2] = b2 * cs + a * sn;
    }
}

// ---------------- softmax over rows of 1024 ----------------
__global__ void softmax_kernel(float* __restrict__ lg) {
    float* row = lg + (size_t)blockIdx.x * L;
    int t = threadIdx.x;
    float vals[4];
    float m = -1e30f;
#pragma unroll
    for (int i = 0; i < 4; i++) { vals[i] = row[t + i * 256]; m = fmaxf(m, vals[i]); }
    __shared__ float red[256];
    red[t] = m; __syncthreads();
    for (int st = 128; st > 0; st >>= 1) {
        if (t < st) red[t] = fmaxf(red[t], red[t + st]);
        __syncthreads();
    }
    m = red[0]; __syncthreads();
    float s = 0.f;
#pragma unroll
    for (int i = 0; i < 4; i++) { vals[i] = __expf(vals[i] - m); s += vals[i]; }
    red[t] = s; __syncthreads();
    for (int st = 128; st > 0; st >>= 1) {
        if (t < st) red[t] += red[t + st];
        __syncthreads();
    }
    float inv = 1.f / red[0];
#pragma unroll
    for (int i = 0; i < 4; i++) row[t + i * 256] = vals[i] * inv;
}

// ---------------- GeGLU ----------------
__global__ void geglu_kernel(float* __restrict__ gate, const float* __restrict__ up) {
    int idx = blockIdx.x * blockDim.x + threadIdx.x;
    if (idx >= BL * FF) return;
    float g = gate[idx];
    float t = 0.7978845608028654f * (g + 0.044715f * g * g * g);
    gate[idx] = 0.5f * g * (1.f + tanhf(t)) * up[idx];
}

// ---------------- final ----------------
__global__ void final_kernel(const float* __restrict__ x, const float* __restrict__ bias,
                             const float* __restrict__ scl, float* __restrict__ out) {
    int idx = blockIdx.x * blockDim.x + threadIdx.x;
    if (idx >= BL * DIM) return;
    int d = idx % DIM;
    out[idx] = (x[idx] * 33.941125496954285f - bias[d]) * scl[d];
}

// ---------------- launcher ----------------
extern "C" void kernel_launch(void* const* d_in, const int* in_sizes, int n_in,
                              void* d_out, int out_size) {
    const float* inputs    = (const float*)d_in[0];
    const float* Wp        = (const float*)d_in[1];
    const float* posemb    = (const float*)d_in[2];
    const float* Wq        = (const float*)d_in[3];
    const float* Wk        = (const float*)d_in[4];
    const float* Wv        = (const float*)d_in[5];
    const float* Wo        = (const float*)d_in[6];
    const float* Wg        = (const float*)d_in[7];
    const float* Wu        = (const float*)d_in[8];
    const float* Wd        = (const float*)d_in[9];
    const float* qn        = (const float*)d_in[10];
    const float* kn        = (const float*)d_in[11];
    const float* vn        = (const float*)d_in[12];
    const float* pre_attn  = (const float*)d_in[13];
    const float* post_attn = (const float*)d_in[14];
    const float* pre_ffw   = (const float*)d_in[15];
    const float* post_ffw  = (const float*)d_in[16];
    const float* std_bias  = (const float*)d_in[17];
    const float* std_scale = (const float*)d_in[18];
    float* out = (float*)d_out;

    float *patches, *x, *h, *q, *k, *v, *att, *o, *logits, *gate, *up;
    cudaGetSymbolAddress((void**)&patches, g_patches);
    cudaGetSymbolAddress((void**)&x, g_x);
    cudaGetSymbolAddress((void**)&h, g_h);
    cudaGetSymbolAddress((void**)&q, g_q);
    cudaGetSymbolAddress((void**)&k, g_k);
    cudaGetSymbolAddress((void**)&v, g_v);
    cudaGetSymbolAddress((void**)&att, g_att);
    cudaGetSymbolAddress((void**)&o, g_o);
    cudaGetSymbolAddress((void**)&logits, g_logits);
    cudaGetSymbolAddress((void**)&gate, g_gate);
    cudaGetSymbolAddress((void**)&up, g_up);

    const float qk_scale = 0.11785113019775793f;  // 1/sqrt(72)

    // entry
    patchify_kernel<<<(BL * PATCHD + 255) / 256, 256>>>(inputs, patches);
    mma_nn<<<dim3(DIM / 128, BL / 128), 256>>>(patches, PATCHD, Wp, DIM, x, DIM,
                                               BL, DIM, PATCHD, 0, 1.f);
    add_posemb_kernel<<<(BL * DIM + 255) / 256, 256>>>(x, posemb);

    for (int i = 0; i < NLAYERS; i++) {
        const float* Wq_i = Wq + (size_t)i * DIM * DIM;
        const float* Wk_i = Wk + (size_t)i * DIM * DIM;
        const float* Wv_i = Wv + (size_t)i * DIM * DIM;
        const float* Wo_i = Wo + (size_t)i * DIM * DIM;
        const float* Wg_i = Wg + (size_t)i * DIM * FF;
        const float* Wu_i = Wu + (size_t)i * DIM * FF;
        const float* Wd_i = Wd + (size_t)i * FF * DIM;

        // attention
        rmsnorm_kernel<<<BL, 256>>>(x, pre_attn + i * DIM, h);
        mma_nn<<<dim3(DIM / 128, BL / 128), 256>>>(h, DIM, Wq_i, DIM, q, DIM,
                                                   BL, DIM, DIM, 0, 1.f);
        mma_nn<<<dim3(DIM / 128, BL / 128), 256>>>(h, DIM, Wk_i, DIM, k, DIM,
                                                   BL, DIM, DIM, 0, 1.f);
        mma_nn<<<dim3(DIM / 128, BL / 128), 256>>>(h, DIM, Wv_i, DIM, v, DIM,
                                                   BL, DIM, DIM, 0, 1.f);
        head_rms_rope_kernel<<<BL * NHEADS / 8, 256>>>(q, qn + i * HDIM, 1);
        head_rms_rope_kernel<<<BL * NHEADS / 8, 256>>>(k, kn + i * HDIM, 1);
        head_rms_rope_kernel<<<BL * NHEADS / 8, 256>>>(v, vn + i * HDIM, 0);
        mma_nt_qk<<<dim3(L / 128, L / 128, BATCH * NHEADS), 256>>>(q, k, logits, qk_scale);
        softmax_kernel<<<BATCH * NHEADS * L, 256>>>(logits);
        mma_nn<<<dim3(1, L / 128, BATCH * NHEADS), 256>>>(logits, L, v, DIM, att, DIM,
                                                          L, HDIM, L, 1, 1.f);
        mma_nn<<<dim3(DIM / 128, BL / 128), 256>>>(att, DIM, Wo_i, DIM, o, DIM,
                                                   BL, DIM, DIM, 0, 1.f);
        resid_rms_add_kernel<<<BL, 256>>>(x, o, post_attn + i * DIM);

        // GeGLU MLP
        rmsnorm_kernel<<<BL, 256>>>(x, pre_ffw + i * DIM, h);
        mma_nn<<<dim3((FF + 127) / 128, BL / 128), 256>>>(h, DIM, Wg_i, FF, gate, FF,
                                                          BL, FF, DIM, 0, 1.f);
        mma_nn<<<dim3((FF + 127) / 128, BL / 128), 256>>>(h, DIM, Wu_i, FF, up, FF,
                                                          BL, FF, DIM, 0, 1.f);
        geglu_kernel<<<(BL * FF + 255) / 256, 256>>>(gate, up);
        mma_nn<<<dim3(DIM / 128, BL / 128), 256>>>(gate, FF, Wd_i, DIM, o, DIM,
                                                   BL, DIM, FF, 0, 1.f);
        resid_rms_add_kernel<<<BL, 256>>>(x, o, post_ffw + i * DIM);
    }

    // exit
    final_kernel<<<(BL * DIM + 255) / 256, 256>>>(x, std_bias, std_scale, out);
}

// round 4
// speedup vs baseline: 2.2715x; 1.2024x over previous
#include <cuda_runtime.h>
#include <cuda_bf16.h>
#include <math.h>

#define BATCH 2
#define L 1024
#define BL 2048          // BATCH * L
#define DIM 1152
#define NHEADS 16
#define HDIM 72
#define FF 4304
#define NLAYERS 4
#define PATCHD 768       // 16*16*3
#define EPS 1e-6f

// ---------------- static scratch (zero-init .bss, no allocation) ----------------
__device__ float g_patches[BL * PATCHD];
__device__ float g_x[BL * DIM];
__device__ float g_h[BL * DIM];
__device__ float g_q[BL * DIM];
__device__ float g_k[BL * DIM];
__device__ float g_v[BL * DIM];
__device__ float g_att[BL * DIM];
__device__ float g_o[BL * DIM];
__device__ float g_logits[(size_t)BATCH * NHEADS * L * L];
__device__ float g_gate[BL * FF];
__device__ float g_up[BL * FF];

// split pair of f32 into packed bf16x2 hi and lo (3xBF16: a*b ~= ah*bh+ah*bl+al*bh)
__device__ __forceinline__ void split2(float x, float y, unsigned& hi2, unsigned& lo2) {
    __nv_bfloat162 h = __floats2bfloat162_rn(x, y);
    float rx = x - __low2float(h);
    float ry = y - __high2float(h);
    __nv_bfloat162 l = __floats2bfloat162_rn(rx, ry);
    hi2 = *reinterpret_cast<unsigned*>(&h);
    lo2 = *reinterpret_cast<unsigned*>(&l);
}
__device__ __forceinline__ void split1(float x, unsigned short& hi, unsigned short& lo) {
    __nv_bfloat16 h = __float2bfloat16(x);
    float r = x - __bfloat162float(h);
    __nv_bfloat16 l = __float2bfloat16(r);
    hi = *reinterpret_cast<unsigned short*>(&h);
    lo = *reinterpret_cast<unsigned short*>(&l);
}

__device__ __forceinline__ void mma_bf16(float c[4], const unsigned a[4], unsigned b0,
                                         unsigned b1) {
    asm volatile(
        "mma.sync.aligned.m16n8k16.row.col.f32.bf16.bf16.f32 "
        "{%0,%1,%2,%3}, {%4,%5,%6,%7}, {%8,%9}, {%0,%1,%2,%3};"
        : "+f"(c[0]), "+f"(c[1]), "+f"(c[2]), "+f"(c[3])
        : "r"(a[0]), "r"(a[1]), "r"(a[2]), "r"(a[3]), "r"(b0), "r"(b1));
}
__device__ __forceinline__ void mma3(float c[4], const unsigned ah[4], const unsigned al[4],
                                     const unsigned bh[2], const unsigned bl[2]) {
    mma_bf16(c, ah, bh[0], bh[1]);
    mma_bf16(c, ah, bl[0], bl[1]);
    mma_bf16(c, al, bh[0], bh[1]);
}

// =====================================================================================
// NN tensor-core GEMM (3xBF16): C[M,N] = alpha * A[M,K] @ B[K,N]
// A row-major (lda), B row-major (ldb), C row-major (ldc).
// Requirements: M % 128 == 0, K % 16 == 0, N % 8 == 0 (bounds on N handled).
// av_mode: blockIdx.z = b*16+n, applies attention PV offsets.
// =====================================================================================
__global__ __launch_bounds__(256) void mma_nn(const float* __restrict__ A, int lda,
                                              const float* __restrict__ B, int ldb,
                                              float* __restrict__ C, int ldc,
                                              int M, int N, int K, int av_mode, float alpha) {
    __shared__ unsigned short Ah[2][128][18], Al[2][128][18];   // [row][k], pad 18
    __shared__ unsigned short Bh[2][128][18], Bl[2][128][18];   // transposed: [n][k]
    const int tid = threadIdx.x;
    if (av_mode) {
        int bn = blockIdx.z, b = bn >> 4, n = bn & 15;
        A += (size_t)bn * L * L;
        B += (size_t)b * L * DIM + n * HDIM;
        C += (size_t)b * L * DIM + n * HDIM;
    }
    const int m0 = blockIdx.y * 128, n0 = blockIdx.x * 128;
    const int aRow = tid >> 1, aK = (tid & 1) * 8;
    const int bK = tid >> 4, bN = (tid & 15) * 8;
    const bool bNvalid = (n0 + bN) < N;
    const float* Ap = A + (size_t)(m0 + aRow) * lda + aK;
    const float* Bp = B + (size_t)bK * ldb + n0 + bN;

    const int lane = tid & 31, warp = tid >> 5;
    const int g = lane >> 2, t = lane & 3;
    const int wM = (warp >> 2) * 64, wN = (warp & 3) * 32;

    float acc[4][4][4];
#pragma unroll
    for (int i = 0; i < 4; i++)
#pragma unroll
        for (int j = 0; j < 4; j++)
#pragma unroll
            for (int r = 0; r < 4; r++) acc[i][j][r] = 0.f;

    const int nT = K >> 4;
    float4 ra0, ra1, rb0, rb1;

    auto LOAD = [&](int k0) {
        ra0 = *(const float4*)(Ap + k0);
        ra1 = *(const float4*)(Ap + k0 + 4);
        rb0 = bNvalid ? *(const float4*)(Bp + (size_t)k0 * ldb) : make_float4(0, 0, 0, 0);
        rb1 = bNvalid ? *(const float4*)(Bp + (size_t)k0 * ldb + 4) : make_float4(0, 0, 0, 0);
    };
    auto STORE = [&](int buf) {
        unsigned h2, l2;
        split2(ra0.x, ra0.y, h2, l2);
        *(unsigned*)&Ah[buf][aRow][aK] = h2;     *(unsigned*)&Al[buf][aRow][aK] = l2;
        split2(ra0.z, ra0.w, h2, l2);
        *(unsigned*)&Ah[buf][aRow][aK + 2] = h2; *(unsigned*)&Al[buf][aRow][aK + 2] = l2;
        split2(ra1.x, ra1.y, h2, l2);
        *(unsigned*)&Ah[buf][aRow][aK + 4] = h2; *(unsigned*)&Al[buf][aRow][aK + 4] = l2;
        split2(ra1.z, ra1.w, h2, l2);
        *(unsigned*)&Ah[buf][aRow][aK + 6] = h2; *(unsigned*)&Al[buf][aRow][aK + 6] = l2;
        float bvals[8] = {rb0.x, rb0.y, rb0.z, rb0.w, rb1.x, rb1.y, rb1.z, rb1.w};
#pragma unroll
        for (int j = 0; j < 8; j++) {
            unsigned short h, l;
            split1(bvals[j], h, l);
            Bh[buf][bN + j][bK] = h;
            Bl[buf][bN + j][bK] = l;
        }
    };

    LOAD(0); STORE(0); __syncthreads();
    for (int tile = 0; tile < nT; ++tile) {
        int buf = tile & 1;
        if (tile + 1 < nT) LOAD((tile + 1) << 4);
        unsigned ah[4][4], al[4][4], bh[4][2], bl[4][2];
#pragma unroll
        for (int mt = 0; mt < 4; mt++) {
            int r = wM + mt * 16 + g;
            ah[mt][0] = *(unsigned*)&Ah[buf][r][2 * t];
            ah[mt][1] = *(unsigned*)&Ah[buf][r + 8][2 * t];
            ah[mt][2] = *(unsigned*)&Ah[buf][r][2 * t + 8];
            ah[mt][3] = *(unsigned*)&Ah[buf][r + 8][2 * t + 8];
            al[mt][0] = *(unsigned*)&Al[buf][r][2 * t];
            al[mt][1] = *(unsigned*)&Al[buf][r + 8][2 * t];
            al[mt][2] = *(unsigned*)&Al[buf][r][2 * t + 8];
            al[mt][3] = *(unsigned*)&Al[buf][r + 8][2 * t + 8];
        }
#pragma unroll
        for (int nt = 0; nt < 4; nt++) {
            int c = wN + nt * 8 + g;
            bh[nt][0] = *(unsigned*)&Bh[buf][c][2 * t];
            bh[nt][1] = *(unsigned*)&Bh[buf][c][2 * t + 8];
            bl[nt][0] = *(unsigned*)&Bl[buf][c][2 * t];
            bl[nt][1] = *(unsigned*)&Bl[buf][c][2 * t + 8];
        }
#pragma unroll
        for (int mt = 0; mt < 4; mt++)
#pragma unroll
            for (int nt = 0; nt < 4; nt++)
                mma3(acc[mt][nt], ah[mt], al[mt], bh[nt], bl[nt]);
        if (tile + 1 < nT) STORE(buf ^ 1);
        __syncthreads();
    }
#pragma unroll
    for (int mt = 0; mt < 4; mt++) {
        int r = m0 + wM + mt * 16 + g;
#pragma unroll
        for (int nt = 0; nt < 4; nt++) {
            int c = n0 + wN + nt * 8 + 2 * t;
            if (c < N) {
                float* p0 = C + (size_t)r * ldc + c;
                float* p1 = C + (size_t)(r + 8) * ldc + c;
                *(float2*)p0 = make_float2(acc[mt][nt][0] * alpha, acc[mt][nt][1] * alpha);
                *(float2*)p1 = make_float2(acc[mt][nt][2] * alpha, acc[mt][nt][3] * alpha);
            }
        }
    }
}

// =====================================================================================
// NT tensor-core GEMM for QK^T (3xBF16): logits[bn][t][s] = alpha * sum_h Q[t][h]K[s][h]
// Both operands k-contiguous; B stored [n][k] directly.
// =====================================================================================
__global__ __launch_bounds__(256) void mma_nt_qk(const float* __restrict__ Q,
                                                 const float* __restrict__ Km,
                                                 float* __restrict__ Cl, float alpha) {
    __shared__ unsigned short Ah[2][128][18], Al[2][128][18];
    __shared__ unsigned short Bh[2][128][18], Bl[2][128][18];
    const int tid = threadIdx.x;
    const int bn = blockIdx.z, b = bn >> 4, n = bn & 15;
    const float* A = Q + (size_t)b * L * DIM + n * HDIM;
    const float* B = Km + (size_t)b * L * DIM + n * HDIM;
    float* C = Cl + (size_t)bn * L * L;
    const int K = HDIM;

    const int m0 = blockIdx.y * 128, n0 = blockIdx.x * 128;
    const int aRow = tid >> 1, aK = (tid & 1) * 8;
    const float* Ap = A + (size_t)(m0 + aRow) * DIM + aK;
    const float* Bp = B + (size_t)(n0 + aRow) * DIM + aK;

    const int lane = tid & 31, warp = tid >> 5;
    const int g = lane >> 2, t = lane & 3;
    const int wM = (warp >> 2) * 64, wN = (warp & 3) * 32;

    float acc[4][4][4];
#pragma unroll
    for (int i = 0; i < 4; i++)
#pragma unroll
        for (int j = 0; j < 4; j++)
#pragma unroll
            for (int r = 0; r < 4; r++) acc[i][j][r] = 0.f;

    const int nT = (K + 15) >> 4;   // 5 tiles for K=72
    float4 ra0, ra1, rb0, rb1;
    auto LOAD = [&](int k0) {
        bool v0 = (k0 + aK) < K, v1 = (k0 + aK + 4) < K;
        ra0 = v0 ? *(const float4*)(Ap + k0) : make_float4(0, 0, 0, 0);
        ra1 = v1 ? *(const float4*)(Ap + k0 + 4) : make_float4(0, 0, 0, 0);
        rb0 = v0 ? *(const float4*)(Bp + k0) : make_float4(0, 0, 0, 0);
        rb1 = v1 ? *(const float4*)(Bp + k0 + 4) : make_float4(0, 0, 0, 0);
    };
    auto STORE = [&](int buf) {
        unsigned h2, l2;
        split2(ra0.x, ra0.y, h2, l2);
        *(unsigned*)&Ah[buf][aRow][aK] = h2;     *(unsigned*)&Al[buf][aRow][aK] = l2;
        split2(ra0.z, ra0.w, h2, l2);
        *(unsigned*)&Ah[buf][aRow][aK + 2] = h2; *(unsigned*)&Al[buf][aRow][aK + 2] = l2;
        split2(ra1.x, ra1.y, h2, l2);
        *(unsigned*)&Ah[buf][aRow][aK + 4] = h2; *(unsigned*)&Al[buf][aRow][aK + 4] = l2;
        split2(ra1.z, ra1.w, h2, l2);
        *(unsigned*)&Ah[buf][aRow][aK + 6] = h2; *(unsigned*)&Al[buf][aRow][aK + 6] = l2;
        split2(rb0.x, rb0.y, h2, l2);
        *(unsigned*)&Bh[buf][aRow][aK] = h2;     *(unsigned*)&Bl[buf][aRow][aK] = l2;
        split2(rb0.z, rb0.w, h2, l2);
        *(unsigned*)&Bh[buf][aRow][aK + 2] = h2; *(unsigned*)&Bl[buf][aRow][aK + 2] = l2;
        split2(rb1.x, rb1.y, h2, l2);
        *(unsigned*)&Bh[buf][aRow][aK + 4] = h2; *(unsigned*)&Bl[buf][aRow][aK + 4] = l2;
        split2(rb1.z, rb1.w, h2, l2);
        *(unsigned*)&Bh[buf][aRow][aK + 6] = h2; *(unsigned*)&Bl[buf][aRow][aK + 6] = l2;
    };

    LOAD(0); STORE(0); __syncthreads();
    for (int tile = 0; tile < nT; ++tile) {
        int buf = tile & 1;
        if (tile + 1 < nT) LOAD((tile + 1) << 4);
        unsigned ah[4][4], al[4][4], bh[4][2], bl[4][2];
#pragma unroll
        for (int mt = 0; mt < 4; mt++) {
            int r = wM + mt * 16 + g;
            ah[mt][0] = *(unsigned*)&Ah[buf][r][2 * t];
            ah[mt][1] = *(unsigned*)&Ah[buf][r + 8][2 * t];
            ah[mt][2] = *(unsigned*)&Ah[buf][r][2 * t + 8];
            ah[mt][3] = *(unsigned*)&Ah[buf][r + 8][2 * t + 8];
            al[mt][0] = *(unsigned*)&Al[buf][r][2 * t];
            al[mt][1] = *(unsigned*)&Al[buf][r + 8][2 * t];
            al[mt][2] = *(unsigned*)&Al[buf][r][2 * t + 8];
            al[mt][3] = *(unsigned*)&Al[buf][r + 8][2 * t + 8];
        }
#pragma unroll
        for (int nt = 0; nt < 4; nt++) {
            int c = wN + nt * 8 + g;
            bh[nt][0] = *(unsigned*)&Bh[buf][c][2 * t];
            bh[nt][1] = *(unsigned*)&Bh[buf][c][2 * t + 8];
            bl[nt][0] = *(unsigned*)&Bl[buf][c][2 * t];
            bl[nt][1] = *(unsigned*)&Bl[buf][c][2 * t + 8];
        }
#pragma unroll
        for (int mt = 0; mt < 4; mt++)
#pragma unroll
            for (int nt = 0; nt < 4; nt++)
                mma3(acc[mt][nt], ah[mt], al[mt], bh[nt], bl[nt]);
        if (tile + 1 < nT) STORE(buf ^ 1);
        __syncthreads();
    }
#pragma unroll
    for (int mt = 0; mt < 4; mt++) {
        int r = m0 + wM + mt * 16 + g;
#pragma unroll
        for (int nt = 0; nt < 4; nt++) {
            int c = n0 + wN + nt * 8 + 2 * t;
            float* p0 = C + (size_t)r * L + c;
            float* p1 = C + (size_t)(r + 8) * L + c;
            *(float2*)p0 = make_float2(acc[mt][nt][0] * alpha, acc[mt][nt][1] * alpha);
            *(float2*)p1 = make_float2(acc[mt][nt][2] * alpha, acc[mt][nt][3] * alpha);
        }
    }
}

// ---------------- patchify: (2*img-1) gather into [BL, 768] ----------------
__global__ void patchify_kernel(const float* __restrict__ img, float* __restrict__ P) {
    int idx = blockIdx.x * blockDim.x + threadIdx.x;
    if (idx >= BL * PATCHD) return;
    int bl = idx / PATCHD, j = idx % PATCHD;
    int b = bl >> 10, l = bl & 1023;
    int gy = l >> 5, gx = l & 31;
    int py = j / 48, r = j % 48;
    int px = r / 3, c = r % 3;
    int row = gy * 16 + py, col = gx * 16 + px;
    P[idx] = 2.0f * img[(((size_t)b * 512 + row) * 512 + col) * 3 + c] - 1.0f;
}

// ---------------- factorized pos-emb add ----------------
__global__ void add_posemb_kernel(float* __restrict__ x, const float* __restrict__ pe) {
    int idx = blockIdx.x * blockDim.x + threadIdx.x;
    if (idx >= BL * DIM) return;
    int bl = idx / DIM, d = idx % DIM;
    int l = bl & 1023;
    int posx = l & 31, posy = l >> 5;
    x[idx] += pe[(size_t)(posx * 2 + 0) * DIM + d] + pe[(size_t)(posy * 2 + 1) * DIM + d];
}

// ---------------- row RMSNorm ----------------
__global__ void rmsnorm_kernel(const float* __restrict__ in, const float* __restrict__ scale,
                               float* __restrict__ out) {
    int row = blockIdx.x;
    const float* p = in + (size_t)row * DIM;
    float s = 0.f;
    for (int i = threadIdx.x; i < DIM; i += 256) { float v = p[i]; s += v * v; }
    __shared__ float red[256];
    red[threadIdx.x] = s; __syncthreads();
    for (int st = 128; st > 0; st >>= 1) {
        if (threadIdx.x < st) red[threadIdx.x] += red[threadIdx.x + st];
        __syncthreads();
    }
    float rs = rsqrtf(red[0] / (float)DIM + EPS);
    for (int i = threadIdx.x; i < DIM; i += 256)
        out[(size_t)row * DIM + i] = p[i] * rs * (1.f + scale[i]);
}

// ---------------- residual add of RMSNormed branch ----------------
__global__ void resid_rms_add_kernel(float* __restrict__ x, const float* __restrict__ o,
                                     const float* __restrict__ scale) {
    int row = blockIdx.x;
    const float* p = o + (size_t)row * DIM;
    float s = 0.f;
    for (int i = threadIdx.x; i < DIM; i += 256) { float v = p[i]; s += v * v; }
    __shared__ float red[256];
    red[threadIdx.x] = s; __syncthreads();
    for (int st = 128; st > 0; st >>= 1) {
        if (threadIdx.x < st) red[threadIdx.x] += red[threadIdx.x + st];
        __syncthreads();
    }
    float rs = rsqrtf(red[0] / (float)DIM + EPS);
    for (int i = threadIdx.x; i < DIM; i += 256)
        x[(size_t)row * DIM + i] += p[i] * rs * (1.f + scale[i]);
}

// ---------------- per-head RMS (+ optional 2D RoPE), warp per (token, head) ----------------
__global__ void head_rms_rope_kernel(float* __restrict__ t, const float* __restrict__ scale,
                                     int do_rope) {
    int warp = threadIdx.x >> 5, lane = threadIdx.x & 31;
    int item = blockIdx.x * 8 + warp;
    int token = item >> 4;
    int head = item & 15;
    float* p = t + (size_t)token * DIM + head * HDIM;
    float v0 = p[lane];
    float v1 = p[lane + 32];
    float v2 = (lane < 8) ? p[lane + 64] : 0.f;
    float s = v0 * v0 + v1 * v1 + v2 * v2;
#pragma unroll
    for (int off = 16; off; off >>= 1) s += __shfl_xor_sync(0xffffffffu, s, off);
    float rs = rsqrtf(s / (float)HDIM + EPS);
    float n0 = v0 * rs * (1.f + scale[lane]);
    float n1 = v1 * rs * (1.f + scale[lane + 32]);
    float n2 = (lane < 8) ? v2 * rs * (1.f + scale[lane + 64]) : 0.f;
    if (!do_rope) {
        p[lane] = n0; p[lane + 32] = n1;
        if (lane < 8) p[lane + 64] = n2;
        return;
    }
    __shared__ float buf[8][HDIM];
    buf[warp][lane] = n0;
    buf[warp][lane + 32] = n1;
    if (lane < 8) buf[warp][lane + 64] = n2;
    __syncwarp();
    int l = token & 1023;
    float posx = (float)(l & 31), posy = (float)(l >> 5);
    for (int pp = lane; pp < 36; pp += 32) {
        int j = (pp < 18) ? pp : (pp - 18);
        float pos = (pp < 18) ? posx : posy;
        int d1 = (pp < 18) ? pp : (pp + 18);
        int d2 = d1 + 18;
        float ts = powf(100.f, (float)j / 18.f);
        float ang = pos / ts;
        float sn, cs;
        sincosf(ang, &sn, &cs);
        float a = buf[warp][d1], b2 = buf[warp][d2];
        p[d1] = a * cs - b2 * sn;
        p[d2] = b2 * cs + a * sn;
    }
}

// ---------------- softmax over rows of 1024 ----------------
__global__ void softmax_kernel(float* __restrict__ lg) {
    float* row = lg + (size_t)blockIdx.x * L;
    int t = threadIdx.x;
    float vals[4];
    float m = -1e30f;
#pragma unroll
    for (int i = 0; i < 4; i++) { vals[i] = row[t + i * 256]; m = fmaxf(m, vals[i]); }
    __shared__ float red[256];
    red[t] = m; __syncthreads();
    for (int st = 128; st > 0; st >>= 1) {
        if (t < st) red[t] = fmaxf(red[t], red[t + st]);
        __syncthreads();
    }
    m = red[0]; __syncthreads();
    float s = 0.f;
#pragma unroll
    for (int i = 0; i < 4; i++) { vals[i] = __expf(vals[i] - m); s += vals[i]; }
    red[t] = s; __syncthreads();
    for (int st = 128; st > 0; st >>= 1) {
        if (t < st) red[t] += red[t + st];
        __syncthreads();
    }
    float inv = 1.f / red[0];
#pragma unroll
    for (int i = 0; i < 4; i++) row[t + i * 256] = vals[i] * inv;
}

// ---------------- GeGLU ----------------
__global__ void geglu_kernel(float* __restrict__ gate, const float* __restrict__ up) {
    int idx = blockIdx.x * blockDim.x + threadIdx.x;
    if (idx >= BL * FF) return;
    float g = gate[idx];
    float t = 0.7978845608028654f * (g + 0.044715f * g * g * g);
    gate[idx] = 0.5f * g * (1.f + tanhf(t)) * up[idx];
}

// ---------------- final ----------------
__global__ void final_kernel(const float* __restrict__ x, const float* __restrict__ bias,
                             const float* __restrict__ scl, float* __restrict__ out) {
    int idx = blockIdx.x * blockDim.x + threadIdx.x;
    if (idx >= BL * DIM) return;
    int d = idx % DIM;
    out[idx] = (x[idx] * 33.941125496954285f - bias[d]) * scl[d];
}

// ---------------- launcher ----------------
extern "C" void kernel_launch(void* const* d_in, const int* in_sizes, int n_in,
                              void* d_out, int out_size) {
    const float* inputs    = (const float*)d_in[0];
    const float* Wp        = (const float*)d_in[1];
    const float* posemb    = (const float*)d_in[2];
    const float* Wq        = (const float*)d_in[3];
    const float* Wk        = (const float*)d_in[4];
    const float* Wv        = (const float*)d_in[5];
    const float* Wo        = (const float*)d_in[6];
    const float* Wg        = (const float*)d_in[7];
    const float* Wu        = (const float*)d_in[8];
    const float* Wd        = (const float*)d_in[9];
    const float* qn        = (const float*)d_in[10];
    const float* kn        = (const float*)d_in[11];
    const float* vn        = (const float*)d_in[12];
    const float* pre_attn  = (const float*)d_in[13];
    const float* post_attn = (const float*)d_in[14];
    const float* pre_ffw   = (const float*)d_in[15];
    const float* post_ffw  = (const float*)d_in[16];
    const float* std_bias  = (const float*)d_in[17];
    const float* std_scale = (const float*)d_in[18];
    float* out = (float*)d_out;

    float *patches, *x, *h, *q, *k, *v, *att, *o, *logits, *gate, *up;
    cudaGetSymbolAddress((void**)&patches, g_patches);
    cudaGetSymbolAddress((void**)&x, g_x);
    cudaGetSymbolAddress((void**)&h, g_h);
    cudaGetSymbolAddress((void**)&q, g_q);
    cudaGetSymbolAddress((void**)&k, g_k);
    cudaGetSymbolAddress((void**)&v, g_v);
    cudaGetSymbolAddress((void**)&att, g_att);
    cudaGetSymbolAddress((void**)&o, g_o);
    cudaGetSymbolAddress((void**)&logits, g_logits);
    cudaGetSymbolAddress((void**)&gate, g_gate);
    cudaGetSymbolAddress((void**)&up, g_up);

    const float qk_scale = 0.11785113019775793f;  // 1/sqrt(72)

    // entry
    patchify_kernel<<<(BL * PATCHD + 255) / 256, 256>>>(inputs, patches);
    mma_nn<<<dim3(DIM / 128, BL / 128), 256>>>(patches, PATCHD, Wp, DIM, x, DIM,
                                               BL, DIM, PATCHD, 0, 1.f);
    add_posemb_kernel<<<(BL * DIM + 255) / 256, 256>>>(x, posemb);

    for (int i = 0; i < NLAYERS; i++) {
        const float* Wq_i = Wq + (size_t)i * DIM * DIM;
        const float* Wk_i = Wk + (size_t)i * DIM * DIM;
        const float* Wv_i = Wv + (size_t)i * DIM * DIM;
        const float* Wo_i = Wo + (size_t)i * DIM * DIM;
        const float* Wg_i = Wg + (size_t)i * DIM * FF;
        const float* Wu_i = Wu + (size_t)i * DIM * FF;
        const float* Wd_i = Wd + (size_t)i * FF * DIM;

        // attention
        rmsnorm_kernel<<<BL, 256>>>(x, pre_attn + i * DIM, h);
        mma_nn<<<dim3(DIM / 128, BL / 128), 256>>>(h, DIM, Wq_i, DIM, q, DIM,
                                                   BL, DIM, DIM, 0, 1.f);
        mma_nn<<<dim3(DIM / 128, BL / 128), 256>>>(h, DIM, Wk_i, DIM, k, DIM,
                                                   BL, DIM, DIM, 0, 1.f);
        mma_nn<<<dim3(DIM / 128, BL / 128), 256>>>(h, DIM, Wv_i, DIM, v, DIM,
                                                   BL, DIM, DIM, 0, 1.f);
        head_rms_rope_kernel<<<BL * NHEADS / 8, 256>>>(q, qn + i * HDIM, 1);
        head_rms_rope_kernel<<<BL * NHEADS / 8, 256>>>(k, kn + i * HDIM, 1);
        head_rms_rope_kernel<<<BL * NHEADS / 8, 256>>>(v, vn + i * HDIM, 0);
        mma_nt_qk<<<dim3(L / 128, L / 128, BATCH * NHEADS), 256>>>(q, k, logits, qk_scale);
        softmax_kernel<<<BATCH * NHEADS * L, 256>>>(logits);
        mma_nn<<<dim3(1, L / 128, BATCH * NHEADS), 256>>>(logits, L, v, DIM, att, DIM,
                                                          L, HDIM, L, 1, 1.f);
        mma_nn<<<dim3(DIM / 128, BL / 128), 256>>>(att, DIM, Wo_i, DIM, o, DIM,
                                                   BL, DIM, DIM, 0, 1.f);
        resid_rms_add_kernel<<<BL, 256>>>(x, o, post_attn + i * DIM);

        // GeGLU MLP
        rmsnorm_kernel<<<BL, 256>>>(x, pre_ffw + i * DIM, h);
        mma_nn<<<dim3((FF + 127) / 128, BL / 128), 256>>>(h, DIM, Wg_i, FF, gate, FF,
                                                          BL, FF, DIM, 0, 1.f);
        mma_nn<<<dim3((FF + 127) / 128, BL / 128), 256>>>(h, DIM, Wu_i, FF, up, FF,
                                                          BL, FF, DIM, 0, 1.f);
        geglu_kernel<<<(BL * FF + 255) / 256, 256>>>(gate, up);
        mma_nn<<<dim3(DIM / 128, BL / 128), 256>>>(gate, FF, Wd_i, DIM, o, DIM,
                                                   BL, DIM, FF, 0, 1.f);
        resid_rms_add_kernel<<<BL, 256>>>(x, o, post_ffw + i * DIM);
    }

    // exit
    final_kernel<<<(BL * DIM + 255) / 256, 256>>>(x, std_bias, std_scale, out);
}

// round 6
// speedup vs baseline: 2.7751x; 1.2217x over previous
#include <cuda_runtime.h>
#include <cuda_bf16.h>
#include <math.h>

#define BATCH 2
#define L 1024
#define BL 2048
#define DIM 1152
#define NHEADS 16
#define HDIM 72
#define HPAD 80
#define FF 4304
#define NLAYERS 4
#define PATCHD 768
#define EPS 1e-6f

typedef __nv_bfloat16 bf16;

// ---------------- f32 scratch ----------------
__device__ float g_x[BL * DIM];
__device__ float g_q[BL * DIM];
__device__ float g_k[BL * DIM];
__device__ float g_v[BL * DIM];
__device__ float g_o[BL * DIM];
__device__ float g_gate[BL * FF];
__device__ float g_up[BL * FF];
__device__ float g_logits[(size_t)BATCH * NHEADS * L * L];

// ---------------- bf16 hi/lo activation scratch ----------------
__device__ bf16 g_patH[BL * PATCHD], g_patL[BL * PATCHD];
__device__ bf16 g_hH[BL * DIM], g_hL[BL * DIM];
__device__ bf16 g_qpH[BL * NHEADS * HPAD], g_qpL[BL * NHEADS * HPAD];
__device__ bf16 g_kpH[BL * NHEADS * HPAD], g_kpL[BL * NHEADS * HPAD];
__device__ bf16 g_vtH[BATCH * NHEADS * HDIM * L], g_vtL[BATCH * NHEADS * HDIM * L];
__device__ bf16 g_pH[(size_t)BATCH * NHEADS * L * L], g_pL[(size_t)BATCH * NHEADS * L * L];
__device__ bf16 g_attH[BL * DIM], g_attL[BL * DIM];
__device__ bf16 g_gH[BL * FF], g_gL[BL * FF];

// ---------------- pre-split transposed weights [N][K] ----------------
__device__ bf16 g_WpH[DIM * PATCHD], g_WpL[DIM * PATCHD];
__device__ bf16 g_WqH[NLAYERS * DIM * DIM], g_WqL[NLAYERS * DIM * DIM];
__device__ bf16 g_WkH[NLAYERS * DIM * DIM], g_WkL[NLAYERS * DIM * DIM];
__device__ bf16 g_WvH[NLAYERS * DIM * DIM], g_WvL[NLAYERS * DIM * DIM];
__device__ bf16 g_WoH[NLAYERS * DIM * DIM], g_WoL[NLAYERS * DIM * DIM];
__device__ bf16 g_WgH[(size_t)NLAYERS * FF * DIM], g_WgL[(size_t)NLAYERS * FF * DIM];
__device__ bf16 g_WuH[(size_t)NLAYERS * FF * DIM], g_WuL[(size_t)NLAYERS * FF * DIM];
__device__ bf16 g_WdH[(size_t)NLAYERS * DIM * FF], g_WdL[(size_t)NLAYERS * DIM * FF];

__device__ __forceinline__ void splitStore(float v, bf16* H, bf16* Lo, size_t idx) {
    bf16 h = __float2bfloat16(v);
    H[idx] = h;
    Lo[idx] = __float2bfloat16(v - __bfloat162float(h));
}

__device__ __forceinline__ void mma_bf16(float c[4], const unsigned a[4], unsigned b0,
                                         unsigned b1) {
    asm volatile(
        "mma.sync.aligned.m16n8k16.row.col.f32.bf16.bf16.f32 "
        "{%0,%1,%2,%3}, {%4,%5,%6,%7}, {%8,%9}, {%0,%1,%2,%3};"
        : "+f"(c[0]), "+f"(c[1]), "+f"(c[2]), "+f"(c[3])
        : "r"(a[0]), "r"(a[1]), "r"(a[2]), "r"(a[3]), "r"(b0), "r"(b1));
}
__device__ __forceinline__ void ldsm4(unsigned addr, unsigned& r0, unsigned& r1, unsigned& r2,
                                      unsigned& r3) {
    asm volatile("ldmatrix.sync.aligned.m8n8.x4.shared.b16 {%0,%1,%2,%3}, [%4];"
                 : "=r"(r0), "=r"(r1), "=r"(r2), "=r"(r3)
                 : "r"(addr));
}

// =====================================================================================
// prepack: transpose W[K][N] -> hi/lo bf16 [N][K]
// =====================================================================================
__global__ void prepack_kernel(const float* __restrict__ W, bf16* __restrict__ H,
                               bf16* __restrict__ Lo, int K, int N) {
    __shared__ float t[32][33];
    int tx = threadIdx.x, ty = threadIdx.y;
    int n0 = blockIdx.x * 32, k0 = blockIdx.y * 32;
#pragma unroll
    for (int j = 0; j < 4; j++) {
        int k = k0 + ty + j * 8, n = n0 + tx;
        if (k < K && n < N) t[ty + j * 8][tx] = W[(size_t)k * N + n];
    }
    __syncthreads();
#pragma unroll
    for (int j = 0; j < 4; j++) {
        int n = n0 + ty + j * 8, k = k0 + tx;
        if (k < K && n < N) {
            float v = t[tx][ty + j * 8];
            splitStore(v, H, Lo, (size_t)n * K + k);
        }
    }
}

// =====================================================================================
// unified NT tensor-core GEMM (3xBF16, pre-split operands, ldmatrix consumer)
//   C[M,N] = alpha * A[M,K] @ B[N,K]^T    (both k-contiguous)
// mode 0: plain, C f32.   mode 1: QK (z=bn).   mode 2: PV (z=bn, bf16 hi/lo out).
// =====================================================================================
__global__ __launch_bounds__(256) void gemm_kernel(
    const bf16* __restrict__ Ah, const bf16* __restrict__ Al,
    const bf16* __restrict__ Bh, const bf16* __restrict__ Bl,
    float* __restrict__ Cf, bf16* __restrict__ CoH, bf16* __restrict__ CoL,
    int lda, int ldb, int ldc, int M, int N, int K, int mode, float alpha) {
    __shared__ __align__(16) unsigned short sm[2][4][128][16];
    const int tid = threadIdx.x;

    size_t coBase = 0;
    if (mode == 1) {
        int bn = blockIdx.z, b = bn >> 4, n = bn & 15;
        size_t off = ((size_t)b * L * NHEADS + n) * HPAD;
        Ah += off; Al += off; Bh += off; Bl += off;
        Cf += (size_t)bn * L * L;
    } else if (mode == 2) {
        int bn = blockIdx.z, b = bn >> 4, n = bn & 15;
        Ah += (size_t)bn * L * L; Al += (size_t)bn * L * L;
        Bh += (size_t)bn * HDIM * L; Bl += (size_t)bn * HDIM * L;
        coBase = (size_t)b * L * DIM + n * HDIM;
    }

    const int m0 = blockIdx.y * 128, n0 = blockIdx.x * 128;
    const int aRow = tid >> 1, aK = (tid & 1) * 8;
    const int physSt = (aK >> 3) ^ ((aRow >> 2) & 1);
    const bf16* ApH = Ah + (size_t)(m0 + aRow) * lda + aK;
    const bf16* ApL = Al + (size_t)(m0 + aRow) * lda + aK;
    const int gn = n0 + aRow;
    const bool bValid = gn < N;
    const bf16* BpH = Bh + (size_t)gn * ldb + aK;
    const bf16* BpL = Bl + (size_t)gn * ldb + aK;

    const int lane = tid & 31, warp = tid >> 5;
    const int g = lane >> 2, t = lane & 3;
    const int wM = (warp >> 2) * 64, wN = (warp & 3) * 32;

    // ldmatrix lane offsets (bytes within one buffer)
    const int lr = lane & 15, kc = lane >> 4;
    unsigned smBase = (unsigned)__cvta_generic_to_shared(&sm[0][0][0][0]);
    unsigned offA[4], offB[2];
#pragma unroll
    for (int mt = 0; mt < 4; mt++) {
        int r = wM + mt * 16 + lr;
        int ph = kc ^ ((r >> 2) & 1);
        offA[mt] = r * 32 + ph * 16;                       // arr 0 (Ah); +4096 = Al
    }
#pragma unroll
    for (int p = 0; p < 2; p++) {
        int r = wN + p * 16 + lr;
        int ph = kc ^ ((r >> 2) & 1);
        offB[p] = 2 * 4096 + r * 32 + ph * 16;             // arr 2 (Bh); +4096 = Bl
    }

    float acc[4][4][4];
#pragma unroll
    for (int i = 0; i < 4; i++)
#pragma unroll
        for (int j = 0; j < 4; j++)
#pragma unroll
            for (int r = 0; r < 4; r++) acc[i][j][r] = 0.f;

    const int nT = K >> 4;
    uint4 rah, ral, rbh, rbl;
    const uint4 z4 = make_uint4(0, 0, 0, 0);

    auto LOAD = [&](int k0) {
        rah = *(const uint4*)(ApH + k0);
        ral = *(const uint4*)(ApL + k0);
        rbh = bValid ? *(const uint4*)(BpH + k0) : z4;
        rbl = bValid ? *(const uint4*)(BpL + k0) : z4;
    };
    auto STORE = [&](int buf) {
        *(uint4*)&sm[buf][0][aRow][physSt * 8] = rah;
        *(uint4*)&sm[buf][1][aRow][physSt * 8] = ral;
        *(uint4*)&sm[buf][2][aRow][physSt * 8] = rbh;
        *(uint4*)&sm[buf][3][aRow][physSt * 8] = rbl;
    };

    LOAD(0); STORE(0); __syncthreads();
    for (int tile = 0; tile < nT; ++tile) {
        int buf = tile & 1;
        unsigned bo = smBase + buf * 16384;
        if (tile + 1 < nT) LOAD((tile + 1) << 4);
        unsigned a_h[4][4], a_l[4][4], b_h[2][4], b_l[2][4];
#pragma unroll
        for (int mt = 0; mt < 4; mt++) {
            ldsm4(bo + offA[mt], a_h[mt][0], a_h[mt][1], a_h[mt][2], a_h[mt][3]);
            ldsm4(bo + offA[mt] + 4096, a_l[mt][0], a_l[mt][1], a_l[mt][2], a_l[mt][3]);
        }
#pragma unroll
        for (int p = 0; p < 2; p++) {
            ldsm4(bo + offB[p], b_h[p][0], b_h[p][1], b_h[p][2], b_h[p][3]);
            ldsm4(bo + offB[p] + 4096, b_l[p][0], b_l[p][1], b_l[p][2], b_l[p][3]);
        }
#pragma unroll
        for (int mt = 0; mt < 4; mt++)
#pragma unroll
            for (int nt = 0; nt < 4; nt++) {
                int p = nt >> 1, od = nt & 1;
                unsigned bh0 = b_h[p][od], bh1 = b_h[p][od + 2];
                unsigned bl0 = b_l[p][od], bl1 = b_l[p][od + 2];
                mma_bf16(acc[mt][nt], a_h[mt], bh0, bh1);
                mma_bf16(acc[mt][nt], a_h[mt], bl0, bl1);
                mma_bf16(acc[mt][nt], a_l[mt], bh0, bh1);
            }
        if (tile + 1 < nT) STORE(buf ^ 1);
        __syncthreads();
    }

    if (mode == 2) {
#pragma unroll
        for (int mt = 0; mt < 4; mt++) {
            int r = m0 + wM + mt * 16 + g;
#pragma unroll
            for (int nt = 0; nt < 4; nt++) {
                int c = wN + nt * 8 + 2 * t;
                if (c < HDIM) {
                    float v0 = acc[mt][nt][0], v1 = acc[mt][nt][1];
                    float v2 = acc[mt][nt][2], v3 = acc[mt][nt][3];
                    __nv_bfloat162 h01 = __floats2bfloat162_rn(v0, v1);
                    __nv_bfloat162 l01 = __floats2bfloat162_rn(v0 - __low2float(h01),
                                                               v1 - __high2float(h01));
                    __nv_bfloat162 h23 = __floats2bfloat162_rn(v2, v3);
                    __nv_bfloat162 l23 = __floats2bfloat162_rn(v2 - __low2float(h23),
                                                               v3 - __high2float(h23));
                    size_t i0 = coBase + (size_t)r * DIM + c;
                    size_t i1 = coBase + (size_t)(r + 8) * DIM + c;
                    *(unsigned*)&CoH[i0] = *(unsigned*)&h01;
                    *(unsigned*)&CoL[i0] = *(unsigned*)&l01;
                    *(unsigned*)&CoH[i1] = *(unsigned*)&h23;
                    *(unsigned*)&CoL[i1] = *(unsigned*)&l23;
                }
            }
        }
    } else {
#pragma unroll
        for (int mt = 0; mt < 4; mt++) {
            int r = m0 + wM + mt * 16 + g;
#pragma unroll
            for (int nt = 0; nt < 4; nt++) {
                int c = n0 + wN + nt * 8 + 2 * t;
                if (c < N) {
                    float* p0 = Cf + (size_t)r * ldc + c;
                    float* p1 = Cf + (size_t)(r + 8) * ldc + c;
                    *(float2*)p0 = make_float2(acc[mt][nt][0] * alpha, acc[mt][nt][1] * alpha);
                    *(float2*)p1 = make_float2(acc[mt][nt][2] * alpha, acc[mt][nt][3] * alpha);
                }
            }
        }
    }
}

// ---------------- patchify: (2*img-1) -> hi/lo bf16 [BL][768] ----------------
__global__ void patchify_kernel(const float* __restrict__ img, bf16* __restrict__ PH,
                                bf16* __restrict__ PL) {
    int idx = blockIdx.x * blockDim.x + threadIdx.x;
    if (idx >= BL * PATCHD) return;
    int bl = idx / PATCHD, j = idx % PATCHD;
    int b = bl >> 10, l = bl & 1023;
    int gy = l >> 5, gx = l & 31;
    int py = j / 48, r = j % 48;
    int px = r / 3, c = r % 3;
    int row = gy * 16 + py, col = gx * 16 + px;
    float v = 2.0f * img[(((size_t)b * 512 + row) * 512 + col) * 3 + c] - 1.0f;
    splitStore(v, PH, PL, idx);
}

// ---------------- factorized pos-emb add ----------------
__global__ void add_posemb_kernel(float* __restrict__ x, const float* __restrict__ pe) {
    int idx = blockIdx.x * blockDim.x + threadIdx.x;
    if (idx >= BL * DIM) return;
    int bl = idx / DIM, d = idx % DIM;
    int l = bl & 1023;
    int posx = l & 31, posy = l >> 5;
    x[idx] += pe[(size_t)(posx * 2 + 0) * DIM + d] + pe[(size_t)(posy * 2 + 1) * DIM + d];
}

// ---------------- row RMSNorm -> hi/lo bf16 ----------------
__global__ void rmsnorm_kernel(const float* __restrict__ in, const float* __restrict__ scale,
                               bf16* __restrict__ outH, bf16* __restrict__ outL) {
    int row = blockIdx.x;
    const float* p = in + (size_t)row * DIM;
    float s = 0.f;
    for (int i = threadIdx.x; i < DIM; i += 256) { float v = p[i]; s += v * v; }
    __shared__ float red[256];
    red[threadIdx.x] = s; __syncthreads();
    for (int st = 128; st > 0; st >>= 1) {
        if (threadIdx.x < st) red[threadIdx.x] += red[threadIdx.x + st];
        __syncthreads();
    }
    float rs = rsqrtf(red[0] / (float)DIM + EPS);
    for (int i = threadIdx.x; i < DIM; i += 256)
        splitStore(p[i] * rs * (1.f + scale[i]), outH, outL, (size_t)row * DIM + i);
}

// ---------------- residual add of RMSNormed branch (f32) ----------------
__global__ void resid_rms_add_kernel(float* __restrict__ x, const float* __restrict__ o,
                                     const float* __restrict__ scale) {
    int row = blockIdx.x;
    const float* p = o + (size_t)row * DIM;
    float s = 0.f;
    for (int i = threadIdx.x; i < DIM; i += 256) { float v = p[i]; s += v * v; }
    __shared__ float red[256];
    red[threadIdx.x] = s; __syncthreads();
    for (int st = 128; st > 0; st >>= 1) {
        if (threadIdx.x < st) red[threadIdx.x] += red[threadIdx.x + st];
        __syncthreads();
    }
    float rs = rsqrtf(red[0] / (float)DIM + EPS);
    for (int i = threadIdx.x; i < DIM; i += 256)
        x[(size_t)row * DIM + i] += p[i] * rs * (1.f + scale[i]);
}

// ---------------- per-head RMS (+2D RoPE) -> padded hi/lo (q/k) or transposed (v) --------
__global__ void head_finish_kernel(const float* __restrict__ src,
                                   const float* __restrict__ scale,
                                   bf16* __restrict__ outH, bf16* __restrict__ outL,
                                   int do_rope, int v_mode) {
    int warp = threadIdx.x >> 5, lane = threadIdx.x & 31;
    int item = blockIdx.x * 8 + warp;
    int token = item >> 4;
    int head = item & 15;
    const float* p = src + (size_t)token * DIM + head * HDIM;
    float v0 = p[lane];
    float v1 = p[lane + 32];
    float v2 = (lane < 8) ? p[lane + 64] : 0.f;
    float s = v0 * v0 + v1 * v1 + v2 * v2;
#pragma unroll
    for (int off = 16; off; off >>= 1) s += __shfl_xor_sync(0xffffffffu, s, off);
    float rs = rsqrtf(s / (float)HDIM + EPS);
    __shared__ float buf[8][HDIM];
    buf[warp][lane] = v0 * rs * (1.f + scale[lane]);
    buf[warp][lane + 32] = v1 * rs * (1.f + scale[lane + 32]);
    if (lane < 8) buf[warp][lane + 64] = v2 * rs * (1.f + scale[lane + 64]);
    __syncwarp();
    if (do_rope) {
        int l = token & 1023;
        float posx = (float)(l & 31), posy = (float)(l >> 5);
        for (int pp = lane; pp < 36; pp += 32) {
            int j = (pp < 18) ? pp : (pp - 18);
            float pos = (pp < 18) ? posx : posy;
            int d1 = (pp < 18) ? pp : (pp + 18);
            int d2 = d1 + 18;
            float ts = powf(100.f, (float)j / 18.f);
            float ang = pos / ts;
            float sn, cs;
            sincosf(ang, &sn, &cs);
            float a = buf[warp][d1], b2 = buf[warp][d2];
            buf[warp][d1] = a * cs - b2 * sn;
            buf[warp][d2] = b2 * cs + a * sn;
        }
        __syncwarp();
    }
    if (!v_mode) {
        size_t base = ((size_t)token * NHEADS + head) * HPAD;
        splitStore(buf[warp][lane], outH, outL, base + lane);
        splitStore(buf[warp][lane + 32], outH, outL, base + lane + 32);
        if (lane < 8) splitStore(buf[warp][lane + 64], outH, outL, base + lane + 64);
    } else {
        int b = token >> 10, l = token & 1023;
        size_t base = ((size_t)(b * NHEADS + head) * HDIM) * L + l;
        splitStore(buf[warp][lane], outH, outL, base + (size_t)lane * L);
        splitStore(buf[warp][lane + 32], outH, outL, base + (size_t)(lane + 32) * L);
        if (lane < 8) splitStore(buf[warp][lane + 64], outH, outL, base + (size_t)(lane + 64) * L);
    }
}

// ---------------- softmax over rows of 1024 -> hi/lo bf16 probs ----------------
__global__ void softmax_kernel(const float* __restrict__ lg, bf16* __restrict__ pH,
                               bf16* __restrict__ pL) {
    const float* row = lg + (size_t)blockIdx.x * L;
    size_t ob = (size_t)blockIdx.x * L;
    int t = threadIdx.x;
    float vals[4];
    float m = -1e30f;
#pragma unroll
    for (int i = 0; i < 4; i++) { vals[i] = row[t + i * 256]; m = fmaxf(m, vals[i]); }
    __shared__ float red[256];
    red[t] = m; __syncthreads();
    for (int st = 128; st > 0; st >>= 1) {
        if (t < st) red[t] = fmaxf(red[t], red[t + st]);
        __syncthreads();
    }
    m = red[0]; __syncthreads();
    float s = 0.f;
#pragma unroll
    for (int i = 0; i < 4; i++) { vals[i] = __expf(vals[i] - m); s += vals[i]; }
    red[t] = s; __syncthreads();
    for (int st = 128; st > 0; st >>= 1) {
        if (t < st) red[t] += red[t + st];
        __syncthreads();
    }
    float inv = 1.f / red[0];
#pragma unroll
    for (int i = 0; i < 4; i++) splitStore(vals[i] * inv, pH, pL, ob + t + i * 256);
}

// ---------------- GeGLU -> hi/lo bf16 ----------------
__global__ void geglu_kernel(const float* __restrict__ gate, const float* __restrict__ up,
                             bf16* __restrict__ gH, bf16* __restrict__ gL) {
    int idx = blockIdx.x * blockDim.x + threadIdx.x;
    if (idx >= BL * FF) return;
    float g = gate[idx];
    float t = 0.7978845608028654f * (g + 0.044715f * g * g * g);
    splitStore(0.5f * g * (1.f + tanhf(t)) * up[idx], gH, gL, idx);
}

// ---------------- final ----------------
__global__ void final_kernel(const float* __restrict__ x, const float* __restrict__ bias,
                             const float* __restrict__ scl, float* __restrict__ out) {
    int idx = blockIdx.x * blockDim.x + threadIdx.x;
    if (idx >= BL * DIM) return;
    int d = idx % DIM;
    out[idx] = (x[idx] * 33.941125496954285f - bias[d]) * scl[d];
}

// ---------------- launcher ----------------
extern "C" void kernel_launch(void* const* d_in, const int* in_sizes, int n_in,
                              void* d_out, int out_size) {
    const float* inputs    = (const float*)d_in[0];
    const float* Wp        = (const float*)d_in[1];
    const float* posemb    = (const float*)d_in[2];
    const float* Wq        = (const float*)d_in[3];
    const float* Wk        = (const float*)d_in[4];
    const float* Wv        = (const float*)d_in[5];
    const float* Wo        = (const float*)d_in[6];
    const float* Wg        = (const float*)d_in[7];
    const float* Wu        = (const float*)d_in[8];
    const float* Wd        = (const float*)d_in[9];
    const float* qn        = (const float*)d_in[10];
    const float* kn        = (const float*)d_in[11];
    const float* vn        = (const float*)d_in[12];
    const float* pre_attn  = (const float*)d_in[13];
    const float* post_attn = (const float*)d_in[14];
    const float* pre_ffw   = (const float*)d_in[15];
    const float* post_ffw  = (const float*)d_in[16];
    const float* std_bias  = (const float*)d_in[17];
    const float* std_scale = (const float*)d_in[18];
    float* out = (float*)d_out;

    float *x, *q, *k, *v, *o, *gate, *up, *logits;
    cudaGetSymbolAddress((void**)&x, g_x);
    cudaGetSymbolAddress((void**)&q, g_q);
    cudaGetSymbolAddress((void**)&k, g_k);
    cudaGetSymbolAddress((void**)&v, g_v);
    cudaGetSymbolAddress((void**)&o, g_o);
    cudaGetSymbolAddress((void**)&gate, g_gate);
    cudaGetSymbolAddress((void**)&up, g_up);
    cudaGetSymbolAddress((void**)&logits, g_logits);
    bf16 *patH, *patL, *hH, *hL, *qpH, *qpL, *kpH, *kpL, *vtH, *vtL, *pH, *pL;
    bf16 *attH, *attL, *gH, *gL;
    cudaGetSymbolAddress((void**)&patH, g_patH); cudaGetSymbolAddress((void**)&patL, g_patL);
    cudaGetSymbolAddress((void**)&hH, g_hH);     cudaGetSymbolAddress((void**)&hL, g_hL);
    cudaGetSymbolAddress((void**)&qpH, g_qpH);   cudaGetSymbolAddress((void**)&qpL, g_qpL);
    cudaGetSymbolAddress((void**)&kpH, g_kpH);   cudaGetSymbolAddress((void**)&kpL, g_kpL);
    cudaGetSymbolAddress((void**)&vtH, g_vtH);   cudaGetSymbolAddress((void**)&vtL, g_vtL);
    cudaGetSymbolAddress((void**)&pH, g_pH);     cudaGetSymbolAddress((void**)&pL, g_pL);
    cudaGetSymbolAddress((void**)&attH, g_attH); cudaGetSymbolAddress((void**)&attL, g_attL);
    cudaGetSymbolAddress((void**)&gH, g_gH);     cudaGetSymbolAddress((void**)&gL, g_gL);
    bf16 *WpH, *WpL, *WqH, *WqL, *WkH, *WkL, *WvH, *WvL, *WoH, *WoL;
    bf16 *WgH, *WgL, *WuH, *WuL, *WdH, *WdL;
    cudaGetSymbolAddress((void**)&WpH, g_WpH); cudaGetSymbolAddress((void**)&WpL, g_WpL);
    cudaGetSymbolAddress((void**)&WqH, g_WqH); cudaGetSymbolAddress((void**)&WqL, g_WqL);
    cudaGetSymbolAddress((void**)&WkH, g_WkH); cudaGetSymbolAddress((void**)&WkL, g_WkL);
    cudaGetSymbolAddress((void**)&WvH, g_WvH); cudaGetSymbolAddress((void**)&WvL, g_WvL);
    cudaGetSymbolAddress((void**)&WoH, g_WoH); cudaGetSymbolAddress((void**)&WoL, g_WoL);
    cudaGetSymbolAddress((void**)&WgH, g_WgH); cudaGetSymbolAddress((void**)&WgL, g_WgL);
    cudaGetSymbolAddress((void**)&WuH, g_WuH); cudaGetSymbolAddress((void**)&WuL, g_WuL);
    cudaGetSymbolAddress((void**)&WdH, g_WdH); cudaGetSymbolAddress((void**)&WdL, g_WdL);

    const float qk_scale = 0.11785113019775793f;  // 1/sqrt(72)
    dim3 tb(32, 8);

    // ---- weight prepack (transpose + hi/lo split) ----
    prepack_kernel<<<dim3((DIM + 31) / 32, (PATCHD + 31) / 32), tb>>>(Wp, WpH, WpL, PATCHD, DIM);
    for (int i = 0; i < NLAYERS; i++) {
        size_t so = (size_t)i * DIM * DIM;
        prepack_kernel<<<dim3(36, 36), tb>>>(Wq + so, WqH + so, WqL + so, DIM, DIM);
        prepack_kernel<<<dim3(36, 36), tb>>>(Wk + so, WkH + so, WkL + so, DIM, DIM);
        prepack_kernel<<<dim3(36, 36), tb>>>(Wv + so, WvH + so, WvL + so, DIM, DIM);
        prepack_kernel<<<dim3(36, 36), tb>>>(Wo + so, WoH + so, WoL + so, DIM, DIM);
        size_t fo = (size_t)i * DIM * FF;
        prepack_kernel<<<dim3((FF + 31) / 32, 36), tb>>>(Wg + fo, WgH + fo, WgL + fo, DIM, FF);
        prepack_kernel<<<dim3((FF + 31) / 32, 36), tb>>>(Wu + fo, WuH + fo, WuL + fo, DIM, FF);
        prepack_kernel<<<dim3(36, (FF + 31) / 32), tb>>>(Wd + fo, WdH + fo, WdL + fo, FF, DIM);
    }

    // ---- entry ----
    patchify_kernel<<<(BL * PATCHD + 255) / 256, 256>>>(inputs, patH, patL);
    gemm_kernel<<<dim3(9, 16), 256>>>(patH, patL, WpH, WpL, x, nullptr, nullptr,
                                      PATCHD, PATCHD, DIM, BL, DIM, PATCHD, 0, 1.f);
    add_posemb_kernel<<<(BL * DIM + 255) / 256, 256>>>(x, posemb);

    for (int i = 0; i < NLAYERS; i++) {
        size_t so = (size_t)i * DIM * DIM;
        size_t fo = (size_t)i * DIM * FF;

        // attention
        rmsnorm_kernel<<<BL, 256>>>(x, pre_attn + i * DIM, hH, hL);
        gemm_kernel<<<dim3(9, 16), 256>>>(hH, hL, WqH + so, WqL + so, q, nullptr, nullptr,
                                          DIM, DIM, DIM, BL, DIM, DIM, 0, 1.f);
        gemm_kernel<<<dim3(9, 16), 256>>>(hH, hL, WkH + so, WkL + so, k, nullptr, nullptr,
                                          DIM, DIM, DIM, BL, DIM, DIM, 0, 1.f);
        gemm_kernel<<<dim3(9, 16), 256>>>(hH, hL, WvH + so, WvL + so, v, nullptr, nullptr,
                                          DIM, DIM, DIM, BL, DIM, DIM, 0, 1.f);
        head_finish_kernel<<<BL * NHEADS / 8, 256>>>(q, qn + i * HDIM, qpH, qpL, 1, 0);
        head_finish_kernel<<<BL * NHEADS / 8, 256>>>(k, kn + i * HDIM, kpH, kpL, 1, 0);
        head_finish_kernel<<<BL * NHEADS / 8, 256>>>(v, vn + i * HDIM, vtH, vtL, 0, 1);
        gemm_kernel<<<dim3(8, 8, 32), 256>>>(qpH, qpL, kpH, kpL, logits, nullptr, nullptr,
                                             NHEADS * HPAD, NHEADS * HPAD, L,
                                             L, L, HPAD, 1, qk_scale);
        softmax_kernel<<<BATCH * NHEADS * L, 256>>>(logits, pH, pL);
        gemm_kernel<<<dim3(1, 8, 32), 256>>>(pH, pL, vtH, vtL, nullptr, attH, attL,
                                             L, L, 0, L, HDIM, L, 2, 1.f);
        gemm_kernel<<<dim3(9, 16), 256>>>(attH, attL, WoH + so, WoL + so, o, nullptr, nullptr,
                                          DIM, DIM, DIM, BL, DIM, DIM, 0, 1.f);
        resid_rms_add_kernel<<<BL, 256>>>(x, o, post_attn + i * DIM);

        // GeGLU MLP
        rmsnorm_kernel<<<BL, 256>>>(x, pre_ffw + i * DIM, hH, hL);
        gemm_kernel<<<dim3(34, 16), 256>>>(hH, hL, WgH + fo, WgL + fo, gate, nullptr, nullptr,
                                           DIM, DIM, FF, BL, FF, DIM, 0, 1.f);
        gemm_kernel<<<dim3(34, 16), 256>>>(hH, hL, WuH + fo, WuL + fo, up, nullptr, nullptr,
                                           DIM, DIM, FF, BL, FF, DIM, 0, 1.f);
        geglu_kernel<<<(BL * FF + 255) / 256, 256>>>(gate, up, gH, gL);
        gemm_kernel<<<dim3(9, 16), 256>>>(gH, gL, WdH + fo, WdL + fo, o, nullptr, nullptr,
                                          FF, FF, DIM, BL, DIM, FF, 0, 1.f);
        resid_rms_add_kernel<<<BL, 256>>>(x, o, post_ffw + i * DIM);
    }

    // exit
    final_kernel<<<(BL * DIM + 255) / 256, 256>>>(x, std_bias, std_scale, out);
}

// round 8
// speedup vs baseline: 3.2112x; 1.1572x over previous
#include <cuda_runtime.h>
#include <cuda_bf16.h>
#include <math.h>

#define BATCH 2
#define L 1024
#define BL 2048
#define DIM 1152
#define NHEADS 16
#define HDIM 72
#define HPAD 80
#define FF 4304
#define NLAYERS 4
#define PATCHD 768
#define EPS 1e-6f

typedef __nv_bfloat16 bf16;

// ---------------- f32 scratch ----------------
__device__ float g_x[BL * DIM];
__device__ float g_q[BL * DIM];
__device__ float g_k[BL * DIM];
__device__ float g_v[BL * DIM];
__device__ float g_o[BL * DIM];
__device__ float g_gate[BL * FF];
__device__ float g_up[BL * FF];

// ---------------- bf16 hi/lo activation scratch ----------------
__device__ bf16 g_patH[BL * PATCHD], g_patL[BL * PATCHD];
__device__ bf16 g_hH[BL * DIM], g_hL[BL * DIM];
__device__ bf16 g_qpH[BL * NHEADS * HPAD], g_qpL[BL * NHEADS * HPAD];
__device__ bf16 g_kpH[BL * NHEADS * HPAD], g_kpL[BL * NHEADS * HPAD];
__device__ bf16 g_vtH[BATCH * NHEADS * HPAD * L], g_vtL[BATCH * NHEADS * HPAD * L];
__device__ bf16 g_attH[BL * DIM], g_attL[BL * DIM];
__device__ bf16 g_gH[BL * FF], g_gL[BL * FF];

// ---------------- pre-split transposed weights [N][K] ----------------
__device__ bf16 g_WpH[DIM * PATCHD], g_WpL[DIM * PATCHD];
__device__ bf16 g_WqH[NLAYERS * DIM * DIM], g_WqL[NLAYERS * DIM * DIM];
__device__ bf16 g_WkH[NLAYERS * DIM * DIM], g_WkL[NLAYERS * DIM * DIM];
__device__ bf16 g_WvH[NLAYERS * DIM * DIM], g_WvL[NLAYERS * DIM * DIM];
__device__ bf16 g_WoH[NLAYERS * DIM * DIM], g_WoL[NLAYERS * DIM * DIM];
__device__ bf16 g_WgH[(size_t)NLAYERS * FF * DIM], g_WgL[(size_t)NLAYERS * FF * DIM];
__device__ bf16 g_WuH[(size_t)NLAYERS * FF * DIM], g_WuL[(size_t)NLAYERS * FF * DIM];
__device__ bf16 g_WdH[(size_t)NLAYERS * DIM * FF], g_WdL[(size_t)NLAYERS * DIM * FF];

__device__ __forceinline__ void splitStore(float v, bf16* H, bf16* Lo, size_t idx) {
    bf16 h = __float2bfloat16(v);
    H[idx] = h;
    Lo[idx] = __float2bfloat16(v - __bfloat162float(h));
}

__device__ __forceinline__ void mma_bf16(float c[4], const unsigned a[4], unsigned b0,
                                         unsigned b1) {
    asm volatile(
        "mma.sync.aligned.m16n8k16.row.col.f32.bf16.bf16.f32 "
        "{%0,%1,%2,%3}, {%4,%5,%6,%7}, {%8,%9}, {%0,%1,%2,%3};"
        : "+f"(c[0]), "+f"(c[1]), "+f"(c[2]), "+f"(c[3])
        : "r"(a[0]), "r"(a[1]), "r"(a[2]), "r"(a[3]), "r"(b0), "r"(b1));
}
__device__ __forceinline__ void mma3(float c[4], const unsigned ah[4], const unsigned al[4],
                                     unsigned bh0, unsigned bh1, unsigned bl0, unsigned bl1) {
    mma_bf16(c, ah, bh0, bh1);
    mma_bf16(c, ah, bl0, bl1);
    mma_bf16(c, al, bh0, bh1);
}
__device__ __forceinline__ void ldsm4(unsigned addr, unsigned& r0, unsigned& r1, unsigned& r2,
                                      unsigned& r3) {
    asm volatile("ldmatrix.sync.aligned.m8n8.x4.shared.b16 {%0,%1,%2,%3}, [%4];"
                 : "=r"(r0), "=r"(r1), "=r"(r2), "=r"(r3)
                 : "r"(addr));
}
__device__ __forceinline__ void pack2(float x, float y, unsigned& hi, unsigned& lo) {
    __nv_bfloat162 h = __floats2bfloat162_rn(x, y);
    __nv_bfloat162 l = __floats2bfloat162_rn(x - __low2float(h), y - __high2float(h));
    hi = *reinterpret_cast<unsigned*>(&h);
    lo = *reinterpret_cast<unsigned*>(&l);
}

// =====================================================================================
// prepack: transpose W[K][N] -> hi/lo bf16 [N][K]
// =====================================================================================
__global__ void prepack_kernel(const float* __restrict__ W, bf16* __restrict__ H,
                               bf16* __restrict__ Lo, int K, int N) {
    __shared__ float t[32][33];
    int tx = threadIdx.x, ty = threadIdx.y;
    int n0 = blockIdx.x * 32, k0 = blockIdx.y * 32;
#pragma unroll
    for (int j = 0; j < 4; j++) {
        int k = k0 + ty + j * 8, n = n0 + tx;
        if (k < K && n < N) t[ty + j * 8][tx] = W[(size_t)k * N + n];
    }
    __syncthreads();
#pragma unroll
    for (int j = 0; j < 4; j++) {
        int n = n0 + ty + j * 8, k = k0 + tx;
        if (k < K && n < N) splitStore(t[tx][ty + j * 8], H, Lo, (size_t)n * K + k);
    }
}

// =====================================================================================
// NT tensor-core GEMM (3xBF16, pre-split operands, ldmatrix consumer)
//   C[M,N] = A[M,K] @ B[N,K]^T   (both k-contiguous), f32 out
// =====================================================================================
__global__ __launch_bounds__(256) void gemm_kernel(
    const bf16* __restrict__ Ah, const bf16* __restrict__ Al,
    const bf16* __restrict__ Bh, const bf16* __restrict__ Bl,
    float* __restrict__ Cf, int lda, int ldb, int ldc, int M, int N, int K) {
    __shared__ __align__(16) unsigned short sm[2][4][128][16];
    const int tid = threadIdx.x;
    const int m0 = blockIdx.y * 128, n0 = blockIdx.x * 128;
    const int aRow = tid >> 1, aK = (tid & 1) * 8;
    const int physSt = (aK >> 3) ^ ((aRow >> 2) & 1);
    const bf16* ApH = Ah + (size_t)(m0 + aRow) * lda + aK;
    const bf16* ApL = Al + (size_t)(m0 + aRow) * lda + aK;
    const int gn = n0 + aRow;
    const bool bValid = gn < N;
    const bf16* BpH = Bh + (size_t)gn * ldb + aK;
    const bf16* BpL = Bl + (size_t)gn * ldb + aK;

    const int lane = tid & 31, warp = tid >> 5;
    const int g = lane >> 2, t = lane & 3;
    const int wM = (warp >> 2) * 64, wN = (warp & 3) * 32;
    const int lr = lane & 15, kc = lane >> 4;
    unsigned smBase = (unsigned)__cvta_generic_to_shared(&sm[0][0][0][0]);
    unsigned offA[4], offB[2];
#pragma unroll
    for (int mt = 0; mt < 4; mt++) {
        int r = wM + mt * 16 + lr;
        int ph = kc ^ ((r >> 2) & 1);
        offA[mt] = r * 32 + ph * 16;
    }
#pragma unroll
    for (int p = 0; p < 2; p++) {
        int r = wN + p * 16 + lr;
        int ph = kc ^ ((r >> 2) & 1);
        offB[p] = 2 * 4096 + r * 32 + ph * 16;
    }

    float acc[4][4][4];
#pragma unroll
    for (int i = 0; i < 4; i++)
#pragma unroll
        for (int j = 0; j < 4; j++)
#pragma unroll
            for (int r = 0; r < 4; r++) acc[i][j][r] = 0.f;

    const int nT = K >> 4;
    uint4 rah, ral, rbh, rbl;
    const uint4 z4 = make_uint4(0, 0, 0, 0);
    auto LOAD = [&](int k0) {
        rah = *(const uint4*)(ApH + k0);
        ral = *(const uint4*)(ApL + k0);
        rbh = bValid ? *(const uint4*)(BpH + k0) : z4;
        rbl = bValid ? *(const uint4*)(BpL + k0) : z4;
    };
    auto STORE = [&](int buf) {
        *(uint4*)&sm[buf][0][aRow][physSt * 8] = rah;
        *(uint4*)&sm[buf][1][aRow][physSt * 8] = ral;
        *(uint4*)&sm[buf][2][aRow][physSt * 8] = rbh;
        *(uint4*)&sm[buf][3][aRow][physSt * 8] = rbl;
    };

    LOAD(0); STORE(0); __syncthreads();
    for (int tile = 0; tile < nT; ++tile) {
        int buf = tile & 1;
        unsigned bo = smBase + buf * 16384;
        if (tile + 1 < nT) LOAD((tile + 1) << 4);
        unsigned a_h[4][4], a_l[4][4], b_h[2][4], b_l[2][4];
#pragma unroll
        for (int mt = 0; mt < 4; mt++) {
            ldsm4(bo + offA[mt], a_h[mt][0], a_h[mt][1], a_h[mt][2], a_h[mt][3]);
            ldsm4(bo + offA[mt] + 4096, a_l[mt][0], a_l[mt][1], a_l[mt][2], a_l[mt][3]);
        }
#pragma unroll
        for (int p = 0; p < 2; p++) {
            ldsm4(bo + offB[p], b_h[p][0], b_h[p][1], b_h[p][2], b_h[p][3]);
            ldsm4(bo + offB[p] + 4096, b_l[p][0], b_l[p][1], b_l[p][2], b_l[p][3]);
        }
#pragma unroll
        for (int mt = 0; mt < 4; mt++)
#pragma unroll
            for (int nt = 0; nt < 4; nt++) {
                int p = nt >> 1, od = nt & 1;
                mma3(acc[mt][nt], a_h[mt], a_l[mt], b_h[p][od], b_h[p][od + 2],
                     b_l[p][od], b_l[p][od + 2]);
            }
        if (tile + 1 < nT) STORE(buf ^ 1);
        __syncthreads();
    }
#pragma unroll
    for (int mt = 0; mt < 4; mt++) {
        int r = m0 + wM + mt * 16 + g;
#pragma unroll
        for (int nt = 0; nt < 4; nt++) {
            int c = n0 + wN + nt * 8 + 2 * t;
            if (c < N) {
                *(float2*)(Cf + (size_t)r * ldc + c) =
                    make_float2(acc[mt][nt][0], acc[mt][nt][1]);
                *(float2*)(Cf + (size_t)(r + 8) * ldc + c) =
                    make_float2(acc[mt][nt][2], acc[mt][nt][3]);
            }
        }
    }
}

// =====================================================================================
// Flash attention: per (q-tile 128, bn) block. Q pre-scaled. 3xBF16 mma + online softmax.
// Q/K: [token][head][80] hi/lo.  V: [bn][80][L] hi/lo (rows 72..79 zero).
// out: att [token][DIM] bf16 hi/lo.
// =====================================================================================
#define SK_OFF 0
#define SKL_OFF 11264
#define SV_OFF 22528
#define SVL_OFF 33408
#define FLASH_SMEM ((22528 + 21760) * 2)

__global__ __launch_bounds__(256, 1) void flash_kernel(
    const bf16* __restrict__ qH, const bf16* __restrict__ qL,
    const bf16* __restrict__ kH, const bf16* __restrict__ kL,
    const bf16* __restrict__ vH, const bf16* __restrict__ vL,
    bf16* __restrict__ attH, bf16* __restrict__ attL) {
    extern __shared__ __align__(16) unsigned short sm[];
    unsigned short* sKh = sm + SK_OFF;
    unsigned short* sKl = sm + SKL_OFF;
    unsigned short* sVh = sm + SV_OFF;
    unsigned short* sVl = sm + SVL_OFF;
    unsigned smBase = (unsigned)__cvta_generic_to_shared(sm);

    const int tid = threadIdx.x;
    const int qt = blockIdx.x, bn = blockIdx.y;
    const int b = bn >> 4, n = bn & 15;
    const int lane = tid & 31, warp = tid >> 5;
    const int g = lane >> 2, t = lane & 3;
    const int lr = lane & 15, kh = lane >> 4;
    const int qRow0 = warp * 16;

    const size_t qkStride = (size_t)NHEADS * HPAD;  // 1280
    const size_t qBase = ((size_t)(b * L + qt * 128) * NHEADS + n) * HPAD;
    const size_t kBase = ((size_t)(b * L) * NHEADS + n) * HPAD;
    const size_t vBase = ((size_t)bn * HPAD) * L;

    // ---- load Q tile into K smem slots, ldmatrix to registers ----
#pragma unroll
    for (int i = 0; i < 5; i++) {
        int idx = tid + i * 256;
        int r = idx / 10, c8 = (idx % 10) * 8;
        size_t go = qBase + (size_t)r * qkStride + c8;
        *(uint4*)&sKh[r * 88 + c8] = *(const uint4*)(qH + go);
        *(uint4*)&sKl[r * 88 + c8] = *(const uint4*)(qL + go);
    }
    __syncthreads();
    unsigned qh[5][4], ql[5][4];
#pragma unroll
    for (int ch = 0; ch < 5; ch++) {
        unsigned a = smBase + ((qRow0 + lr) * 88 + ch * 16 + kh * 8) * 2;
        ldsm4(a, qh[ch][0], qh[ch][1], qh[ch][2], qh[ch][3]);
        ldsm4(a + SKL_OFF * 2, ql[ch][0], ql[ch][1], ql[ch][2], ql[ch][3]);
    }
    __syncthreads();

    float Oacc[10][4];
#pragma unroll
    for (int i = 0; i < 10; i++)
#pragma unroll
        for (int j = 0; j < 4; j++) Oacc[i][j] = 0.f;
    float mA = -1e30f, mB = -1e30f, lA = 0.f, lB = 0.f;

    for (int st = 0; st < 8; st++) {
        // ---- load K,V tiles ----
#pragma unroll
        for (int i = 0; i < 5; i++) {
            int idx = tid + i * 256;
            int r = idx / 10, c8 = (idx % 10) * 8;
            size_t go = kBase + (size_t)(st * 128 + r) * qkStride + c8;
            *(uint4*)&sKh[r * 88 + c8] = *(const uint4*)(kH + go);
            *(uint4*)&sKl[r * 88 + c8] = *(const uint4*)(kL + go);
            int vr = idx / 16, vc = (idx % 16) * 8;
            size_t gv = vBase + (size_t)vr * L + st * 128 + vc;
            *(uint4*)&sVh[vr * 136 + vc] = *(const uint4*)(vH + gv);
            *(uint4*)&sVl[vr * 136 + vc] = *(const uint4*)(vL + gv);
        }
        __syncthreads();

        // ---- S = Q K^T (scaled; scale folded into Q) ----
        float sacc[16][4];
#pragma unroll
        for (int i = 0; i < 16; i++)
#pragma unroll
            for (int j = 0; j < 4; j++) sacc[i][j] = 0.f;
#pragma unroll
        for (int ch = 0; ch < 5; ch++) {
#pragma unroll
            for (int ng = 0; ng < 8; ng++) {
                unsigned a = smBase + ((ng * 16 + lr) * 88 + ch * 16 + kh * 8) * 2;
                unsigned h0, h1, h2, h3, l0, l1, l2, l3;
                ldsm4(a, h0, h1, h2, h3);
                ldsm4(a + SKL_OFF * 2, l0, l1, l2, l3);
                mma3(sacc[2 * ng], qh[ch], ql[ch], h0, h2, l0, l2);
                mma3(sacc[2 * ng + 1], qh[ch], ql[ch], h1, h3, l1, l3);
            }
        }

        // ---- online softmax ----
        float tmA = -1e30f, tmB = -1e30f;
#pragma unroll
        for (int i = 0; i < 16; i++) {
            tmA = fmaxf(tmA, fmaxf(sacc[i][0], sacc[i][1]));
            tmB = fmaxf(tmB, fmaxf(sacc[i][2], sacc[i][3]));
        }
        tmA = fmaxf(tmA, __shfl_xor_sync(0xffffffffu, tmA, 1));
        tmA = fmaxf(tmA, __shfl_xor_sync(0xffffffffu, tmA, 2));
        tmB = fmaxf(tmB, __shfl_xor_sync(0xffffffffu, tmB, 1));
        tmB = fmaxf(tmB, __shfl_xor_sync(0xffffffffu, tmB, 2));
        float mnA = fmaxf(mA, tmA), mnB = fmaxf(mB, tmB);
        float fA = __expf(mA - mnA), fB = __expf(mB - mnB);
        mA = mnA; mB = mnB;
        float sA = 0.f, sB = 0.f;
#pragma unroll
        for (int i = 0; i < 16; i++) {
            sacc[i][0] = __expf(sacc[i][0] - mnA);
            sacc[i][1] = __expf(sacc[i][1] - mnA);
            sacc[i][2] = __expf(sacc[i][2] - mnB);
            sacc[i][3] = __expf(sacc[i][3] - mnB);
            sA += sacc[i][0] + sacc[i][1];
            sB += sacc[i][2] + sacc[i][3];
        }
        sA += __shfl_xor_sync(0xffffffffu, sA, 1);
        sA += __shfl_xor_sync(0xffffffffu, sA, 2);
        sB += __shfl_xor_sync(0xffffffffu, sB, 1);
        sB += __shfl_xor_sync(0xffffffffu, sB, 2);
        lA = lA * fA + sA;
        lB = lB * fB + sB;
#pragma unroll
        for (int i = 0; i < 10; i++) {
            Oacc[i][0] *= fA; Oacc[i][1] *= fA;
            Oacc[i][2] *= fB; Oacc[i][3] *= fB;
        }

        // ---- O += P V^T ----
#pragma unroll
        for (int kc = 0; kc < 8; kc++) {
            unsigned ah[4], al[4];
            pack2(sacc[2 * kc][0], sacc[2 * kc][1], ah[0], al[0]);
            pack2(sacc[2 * kc][2], sacc[2 * kc][3], ah[1], al[1]);
            pack2(sacc[2 * kc + 1][0], sacc[2 * kc + 1][1], ah[2], al[2]);
            pack2(sacc[2 * kc + 1][2], sacc[2 * kc + 1][3], ah[3], al[3]);
#pragma unroll
            for (int vg = 0; vg < 5; vg++) {
                unsigned a = smBase + SV_OFF * 2 + ((vg * 16 + lr) * 136 + kc * 16 + kh * 8) * 2;
                unsigned h0, h1, h2, h3, l0, l1, l2, l3;
                ldsm4(a, h0, h1, h2, h3);
                ldsm4(a + (SVL_OFF - SV_OFF) * 2, l0, l1, l2, l3);
                mma3(Oacc[2 * vg], ah, al, h0, h2, l0, l2);
                mma3(Oacc[2 * vg + 1], ah, al, h1, h3, l1, l3);
            }
        }
        __syncthreads();
    }

    // ---- epilogue ----
    float invA = 1.f / lA, invB = 1.f / lB;
    int row0 = b * L + qt * 128 + qRow0 + g;
#pragma unroll
    for (int nt = 0; nt < 9; nt++) {
        int c = n * HDIM + nt * 8 + 2 * t;
        size_t i0 = (size_t)row0 * DIM + c;
        size_t i1 = (size_t)(row0 + 8) * DIM + c;
        splitStore(Oacc[nt][0] * invA, attH, attL, i0);
        splitStore(Oacc[nt][1] * invA, attH, attL, i0 + 1);
        splitStore(Oacc[nt][2] * invB, attH, attL, i1);
        splitStore(Oacc[nt][3] * invB, attH, attL, i1 + 1);
    }
}

// ---------------- patchify ----------------
__global__ void patchify_kernel(const float* __restrict__ img, bf16* __restrict__ PH,
                                bf16* __restrict__ PL) {
    int idx = blockIdx.x * blockDim.x + threadIdx.x;
    if (idx >= BL * PATCHD) return;
    int bl = idx / PATCHD, j = idx % PATCHD;
    int b = bl >> 10, l = bl & 1023;
    int gy = l >> 5, gx = l & 31;
    int py = j / 48, r = j % 48;
    int px = r / 3, c = r % 3;
    int row = gy * 16 + py, col = gx * 16 + px;
    float v = 2.0f * img[(((size_t)b * 512 + row) * 512 + col) * 3 + c] - 1.0f;
    splitStore(v, PH, PL, idx);
}

// ---------------- pos-emb add ----------------
__global__ void add_posemb_kernel(float* __restrict__ x, const float* __restrict__ pe) {
    int idx = blockIdx.x * blockDim.x + threadIdx.x;
    if (idx >= BL * DIM) return;
    int bl = idx / DIM, d = idx % DIM;
    int l = bl & 1023;
    int posx = l & 31, posy = l >> 5;
    x[idx] += pe[(size_t)(posx * 2 + 0) * DIM + d] + pe[(size_t)(posy * 2 + 1) * DIM + d];
}

// ---------------- row RMSNorm -> hi/lo bf16 ----------------
__global__ void rmsnorm_kernel(const float* __restrict__ in, const float* __restrict__ scale,
                               bf16* __restrict__ outH, bf16* __restrict__ outL) {
    int row = blockIdx.x;
    const float* p = in + (size_t)row * DIM;
    float s = 0.f;
    for (int i = threadIdx.x; i < DIM; i += 256) { float v = p[i]; s += v * v; }
    __shared__ float red[256];
    red[threadIdx.x] = s; __syncthreads();
    for (int st = 128; st > 0; st >>= 1) {
        if (threadIdx.x < st) red[threadIdx.x] += red[threadIdx.x + st];
        __syncthreads();
    }
    float rs = rsqrtf(red[0] / (float)DIM + EPS);
    for (int i = threadIdx.x; i < DIM; i += 256)
        splitStore(p[i] * rs * (1.f + scale[i]), outH, outL, (size_t)row * DIM + i);
}

// ---------------- residual add of RMSNormed branch ----------------
__global__ void resid_rms_add_kernel(float* __restrict__ x, const float* __restrict__ o,
                                     const float* __restrict__ scale) {
    int row = blockIdx.x;
    const float* p = o + (size_t)row * DIM;
    float s = 0.f;
    for (int i = threadIdx.x; i < DIM; i += 256) { float v = p[i]; s += v * v; }
    __shared__ float red[256];
    red[threadIdx.x] = s; __syncthreads();
    for (int st = 128; st > 0; st >>= 1) {
        if (threadIdx.x < st) red[threadIdx.x] += red[threadIdx.x + st];
        __syncthreads();
    }
    float rs = rsqrtf(red[0] / (float)DIM + EPS);
    for (int i = threadIdx.x; i < DIM; i += 256)
        x[(size_t)row * DIM + i] += p[i] * rs * (1.f + scale[i]);
}

// ---------------- per-head RMS (+2D RoPE) -> padded hi/lo (q/k) or V-transposed --------
__global__ void head_finish_kernel(const float* __restrict__ src,
                                   const float* __restrict__ scale,
                                   bf16* __restrict__ outH, bf16* __restrict__ outL,
                                   int do_rope, int v_mode, float premul) {
    int warp = threadIdx.x >> 5, lane = threadIdx.x & 31;
    int item = blockIdx.x * 8 + warp;
    int token = item >> 4;
    int head = item & 15;
    const float* p = src + (size_t)token * DIM + head * HDIM;
    float v0 = p[lane];
    float v1 = p[lane + 32];
    float v2 = (lane < 8) ? p[lane + 64] : 0.f;
    float s = v0 * v0 + v1 * v1 + v2 * v2;
#pragma unroll
    for (int off = 16; off; off >>= 1) s += __shfl_xor_sync(0xffffffffu, s, off);
    float rs = rsqrtf(s / (float)HDIM + EPS) * premul;
    __shared__ float buf[8][HDIM];
    buf[warp][lane] = v0 * rs * (1.f + scale[lane]);
    buf[warp][lane + 32] = v1 * rs * (1.f + scale[lane + 32]);
    if (lane < 8) buf[warp][lane + 64] = v2 * rs * (1.f + scale[lane + 64]);
    __syncwarp();
    if (do_rope) {
        int l = token & 1023;
        float posx = (float)(l & 31), posy = (float)(l >> 5);
        for (int pp = lane; pp < 36; pp += 32) {
            int j = (pp < 18) ? pp : (pp - 18);
            float pos = (pp < 18) ? posx : posy;
            int d1 = (pp < 18) ? pp : (pp + 18);
            int d2 = d1 + 18;
            float ts = powf(100.f, (float)j / 18.f);
            float ang = pos / ts;
            float sn, cs;
            sincosf(ang, &sn, &cs);
            float a = buf[warp][d1], b2 = buf[warp][d2];
            buf[warp][d1] = a * cs - b2 * sn;
            buf[warp][d2] = b2 * cs + a * sn;
        }
        __syncwarp();
    }
    if (!v_mode) {
        size_t base = ((size_t)token * NHEADS + head) * HPAD;
        splitStore(buf[warp][lane], outH, outL, base + lane);
        splitStore(buf[warp][lane + 32], outH, outL, base + lane + 32);
        if (lane < 8) splitStore(buf[warp][lane + 64], outH, outL, base + lane + 64);
    } else {
        int b = token >> 10, l = token & 1023;
        size_t base = ((size_t)(b * NHEADS + head) * HPAD) * L + l;
        splitStore(buf[warp][lane], outH, outL, base + (size_t)lane * L);
        splitStore(buf[warp][lane + 32], outH, outL, base + (size_t)(lane + 32) * L);
        if (lane < 8) splitStore(buf[warp][lane + 64], outH, outL, base + (size_t)(lane + 64) * L);
    }
}

// ---------------- GeGLU -> hi/lo bf16 ----------------
__global__ void geglu_kernel(const float* __restrict__ gate, const float* __restrict__ up,
                             bf16* __restrict__ gH, bf16* __restrict__ gL) {
    int idx = blockIdx.x * blockDim.x + threadIdx.x;
    if (idx >= BL * FF) return;
    float g = gate[idx];
    float t = 0.7978845608028654f * (g + 0.044715f * g * g * g);
    splitStore(0.5f * g * (1.f + tanhf(t)) * up[idx], gH, gL, idx);
}

// ---------------- final ----------------
__global__ void final_kernel(const float* __restrict__ x, const float* __restrict__ bias,
                             const float* __restrict__ scl, float* __restrict__ out) {
    int idx = blockIdx.x * blockDim.x + threadIdx.x;
    if (idx >= BL * DIM) return;
    int d = idx % DIM;
    out[idx] = (x[idx] * 33.941125496954285f - bias[d]) * scl[d];
}

// ---------------- launcher ----------------
extern "C" void kernel_launch(void* const* d_in, const int* in_sizes, int n_in,
                              void* d_out, int out_size) {
    const float* inputs    = (const float*)d_in[0];
    const float* Wp        = (const float*)d_in[1];
    const float* posemb    = (const float*)d_in[2];
    const float* Wq        = (const float*)d_in[3];
    const float* Wk        = (const float*)d_in[4];
    const float* Wv        = (const float*)d_in[5];
    const float* Wo        = (const float*)d_in[6];
    const float* Wg        = (const float*)d_in[7];
    const float* Wu        = (const float*)d_in[8];
    const float* Wd        = (const float*)d_in[9];
    const float* qn        = (const float*)d_in[10];
    const float* kn        = (const float*)d_in[11];
    const float* vn        = (const float*)d_in[12];
    const float* pre_attn  = (const float*)d_in[13];
    const float* post_attn = (const float*)d_in[14];
    const float* pre_ffw   = (const float*)d_in[15];
    const float* post_ffw  = (const float*)d_in[16];
    const float* std_bias  = (const float*)d_in[17];
    const float* std_scale = (const float*)d_in[18];
    float* out = (float*)d_out;

    float *x, *q, *k, *v, *o, *gate, *up;
    cudaGetSymbolAddress((void**)&x, g_x);
    cudaGetSymbolAddress((void**)&q, g_q);
    cudaGetSymbolAddress((void**)&k, g_k);
    cudaGetSymbolAddress((void**)&v, g_v);
    cudaGetSymbolAddress((void**)&o, g_o);
    cudaGetSymbolAddress((void**)&gate, g_gate);
    cudaGetSymbolAddress((void**)&up, g_up);
    bf16 *patH, *patL, *hH, *hL, *qpH, *qpL, *kpH, *kpL, *vtH, *vtL, *attH, *attL, *gH, *gL;
    cudaGetSymbolAddress((void**)&patH, g_patH); cudaGetSymbolAddress((void**)&patL, g_patL);
    cudaGetSymbolAddress((void**)&hH, g_hH);     cudaGetSymbolAddress((void**)&hL, g_hL);
    cudaGetSymbolAddress((void**)&qpH, g_qpH);   cudaGetSymbolAddress((void**)&qpL, g_qpL);
    cudaGetSymbolAddress((void**)&kpH, g_kpH);   cudaGetSymbolAddress((void**)&kpL, g_kpL);
    cudaGetSymbolAddress((void**)&vtH, g_vtH);   cudaGetSymbolAddress((void**)&vtL, g_vtL);
    cudaGetSymbolAddress((void**)&attH, g_attH); cudaGetSymbolAddress((void**)&attL, g_attL);
    cudaGetSymbolAddress((void**)&gH, g_gH);     cudaGetSymbolAddress((void**)&gL, g_gL);
    bf16 *WpH, *WpL, *WqH, *WqL, *WkH, *WkL, *WvH, *WvL, *WoH, *WoL;
    bf16 *WgH, *WgL, *WuH, *WuL, *WdH, *WdL;
    cudaGetSymbolAddress((void**)&WpH, g_WpH); cudaGetSymbolAddress((void**)&WpL, g_WpL);
    cudaGetSymbolAddress((void**)&WqH, g_WqH); cudaGetSymbolAddress((void**)&WqL, g_WqL);
    cudaGetSymbolAddress((void**)&WkH, g_WkH); cudaGetSymbolAddress((void**)&WkL, g_WkL);
    cudaGetSymbolAddress((void**)&WvH, g_WvH); cudaGetSymbolAddress((void**)&WvL, g_WvL);
    cudaGetSymbolAddress((void**)&WoH, g_WoH); cudaGetSymbolAddress((void**)&WoL, g_WoL);
    cudaGetSymbolAddress((void**)&WgH, g_WgH); cudaGetSymbolAddress((void**)&WgL, g_WgL);
    cudaGetSymbolAddress((void**)&WuH, g_WuH); cudaGetSymbolAddress((void**)&WuL, g_WuL);
    cudaGetSymbolAddress((void**)&WdH, g_WdH); cudaGetSymbolAddress((void**)&WdL, g_WdL);

    const float qk_scale = 0.11785113019775793f;  // 1/sqrt(72)
    dim3 tb(32, 8);

    static bool smem_set = false;
    if (!smem_set) {
        cudaFuncSetAttribute(flash_kernel, cudaFuncAttributeMaxDynamicSharedMemorySize,
                             FLASH_SMEM);
        smem_set = true;
    }

    // ---- weight prepack ----
    prepack_kernel<<<dim3((DIM + 31) / 32, (PATCHD + 31) / 32), tb>>>(Wp, WpH, WpL, PATCHD, DIM);
    for (int i = 0; i < NLAYERS; i++) {
        size_t so = (size_t)i * DIM * DIM;
        prepack_kernel<<<dim3(36, 36), tb>>>(Wq + so, WqH + so, WqL + so, DIM, DIM);
        prepack_kernel<<<dim3(36, 36), tb>>>(Wk + so, WkH + so, WkL + so, DIM, DIM);
        prepack_kernel<<<dim3(36, 36), tb>>>(Wv + so, WvH + so, WvL + so, DIM, DIM);
        prepack_kernel<<<dim3(36, 36), tb>>>(Wo + so, WoH + so, WoL + so, DIM, DIM);
        size_t fo = (size_t)i * DIM * FF;
        prepack_kernel<<<dim3((FF + 31) / 32, 36), tb>>>(Wg + fo, WgH + fo, WgL + fo, DIM, FF);
        prepack_kernel<<<dim3((FF + 31) / 32, 36), tb>>>(Wu + fo, WuH + fo, WuL + fo, DIM, FF);
        prepack_kernel<<<dim3(36, (FF + 31) / 32), tb>>>(Wd + fo, WdH + fo, WdL + fo, FF, DIM);
    }

    // ---- entry ----
    patchify_kernel<<<(BL * PATCHD + 255) / 256, 256>>>(inputs, patH, patL);
    gemm_kernel<<<dim3(9, 16), 256>>>(patH, patL, WpH, WpL, x,
                                      PATCHD, PATCHD, DIM, BL, DIM, PATCHD);
    add_posemb_kernel<<<(BL * DIM + 255) / 256, 256>>>(x, posemb);

    for (int i = 0; i < NLAYERS; i++) {
        size_t so = (size_t)i * DIM * DIM;
        size_t fo = (size_t)i * DIM * FF;

        // attention
        rmsnorm_kernel<<<BL, 256>>>(x, pre_attn + i * DIM, hH, hL);
        gemm_kernel<<<dim3(9, 16), 256>>>(hH, hL, WqH + so, WqL + so, q,
                                          DIM, DIM, DIM, BL, DIM, DIM);
        gemm_kernel<<<dim3(9, 16), 256>>>(hH, hL, WkH + so, WkL + so, k,
                                          DIM, DIM, DIM, BL, DIM, DIM);
        gemm_kernel<<<dim3(9, 16), 256>>>(hH, hL, WvH + so, WvL + so, v,
                                          DIM, DIM, DIM, BL, DIM, DIM);
        head_finish_kernel<<<BL * NHEADS / 8, 256>>>(q, qn + i * HDIM, qpH, qpL, 1, 0, qk_scale);
        head_finish_kernel<<<BL * NHEADS / 8, 256>>>(k, kn + i * HDIM, kpH, kpL, 1, 0, 1.f);
        head_finish_kernel<<<BL * NHEADS / 8, 256>>>(v, vn + i * HDIM, vtH, vtL, 0, 1, 1.f);
        flash_kernel<<<dim3(8, 32), 256, FLASH_SMEM>>>(qpH, qpL, kpH, kpL, vtH, vtL,
                                                       attH, attL);
        gemm_kernel<<<dim3(9, 16), 256>>>(attH, attL, WoH + so, WoL + so, o,
                                          DIM, DIM, DIM, BL, DIM, DIM);
        resid_rms_add_kernel<<<BL, 256>>>(x, o, post_attn + i * DIM);

        // GeGLU MLP
        rmsnorm_kernel<<<BL, 256>>>(x, pre_ffw + i * DIM, hH, hL);
        gemm_kernel<<<dim3(34, 16), 256>>>(hH, hL, WgH + fo, WgL + fo, gate,
                                           DIM, DIM, FF, BL, FF, DIM);
        gemm_kernel<<<dim3(34, 16), 256>>>(hH, hL, WuH + fo, WuL + fo, up,
                                           DIM, DIM, FF, BL, FF, DIM);
        geglu_kernel<<<(BL * FF + 255) / 256, 256>>>(gate, up, gH, gL);
        gemm_kernel<<<dim3(9, 16), 256>>>(gH, gL, WdH + fo, WdL + fo, o,
                                          FF, FF, DIM, BL, DIM, FF);
        resid_rms_add_kernel<<<BL, 256>>>(x, o, post_ffw + i * DIM);
    }

    // exit
    final_kernel<<<(BL * DIM + 255) / 256, 256>>>(x, std_bias, std_scale, out);
}